// round 12
// baseline (speedup 1.0000x reference)
#include <cuda_runtime.h>
#include <cstdint>

#define BB  4
#define N0  16384
#define S1V 2048
#define S2V 1024
#define KK  32

// ---------------- device scratch (no allocations allowed) ----------------
__device__ __align__(16) float g_xyz0 [BB * N0  * 3];
__device__ __align__(16) float g_feat0[BB * N0  * 3];
__device__ __align__(16) float g_xyz1 [BB * S1V * 3];
__device__ __align__(16) float g_xyz2 [BB * S2V * 3];
__device__ int   g_nidx1[BB * S1V * KK];
__device__ int   g_nidx2[BB * S2V * KK];
__device__ __align__(16) float g_feat1[BB * S1V * 32];
__device__ __align__(16) float g_bufA [8388608];   // [b][c][s*K+k] channel-major
__device__ __align__(16) float g_bufB [8388608];
__device__ float g_sum[6 * BB * 64];
__device__ float g_sq [6 * BB * 64];
__device__ __align__(16) float g_dist[BB * N0];    // FPS segment-persisted min-dist
__device__ int   g_far[BB];

// ---------------- helpers ----------------
__device__ __forceinline__ unsigned fkey(float f) {
    unsigned u = __float_as_uint(f);
    return u ^ (((unsigned)((int)u >> 31)) | 0x80000000u);
}
__device__ __forceinline__ unsigned long long ullmin2(unsigned long long a, unsigned long long b){return a<b?a:b;}
__device__ __forceinline__ unsigned long long ullmax2(unsigned long long a, unsigned long long b){return a>b?a:b;}

// packed f32x2 ops (Blackwell). Per-lane rounding identical to scalar rn.
__device__ __forceinline__ unsigned long long pk2(float a, float b) {
    unsigned long long r; asm("mov.b64 %0, {%1, %2};" : "=l"(r) : "f"(a), "f"(b)); return r;
}
__device__ __forceinline__ void upk2(unsigned long long v, float& a, float& b) {
    asm("mov.b64 {%0, %1}, %2;" : "=f"(a), "=f"(b) : "l"(v));
}
__device__ __forceinline__ unsigned long long add2(unsigned long long a, unsigned long long b) {
    unsigned long long r; asm("add.rn.f32x2 %0, %1, %2;" : "=l"(r) : "l"(a), "l"(b)); return r;
}
__device__ __forceinline__ unsigned long long mul2(unsigned long long a, unsigned long long b) {
    unsigned long long r; asm("mul.rn.f32x2 %0, %1, %2;" : "=l"(r) : "l"(a), "l"(b)); return r;
}
__device__ __forceinline__ unsigned long long fma2(unsigned long long a, unsigned long long b, unsigned long long c) {
    unsigned long long r; asm("fma.rn.f32x2 %0, %1, %2, %3;" : "=l"(r) : "l"(a), "l"(b), "l"(c)); return r;
}

// warp-uniform reductions (sm_80+)
__device__ __forceinline__ unsigned redux_max(unsigned v) {
    unsigned r; asm volatile("redux.sync.max.u32 %0, %1, 0xffffffff;" : "=r"(r) : "r"(v)); return r;
}
__device__ __forceinline__ unsigned redux_min(unsigned v) {
    unsigned r; asm volatile("redux.sync.min.u32 %0, %1, 0xffffffff;" : "=r"(r) : "r"(v)); return r;
}

// shared-address + cluster comm helpers
__device__ __forceinline__ unsigned smem_u32addr(const void* p) {
    unsigned r;
    asm("{ .reg .u64 t; cvta.to.shared.u64 t, %1; cvt.u32.u64 %0, t; }" : "=r"(r) : "l"(p));
    return r;
}
__device__ __forceinline__ void st_cluster_u32(unsigned laddr, unsigned rank, unsigned v) {
    unsigned pa;
    asm volatile("mapa.shared::cluster.u32 %0, %1, %2;" : "=r"(pa) : "r"(laddr), "r"(rank));
    asm volatile("st.shared::cluster.u32 [%0], %1;" :: "r"(pa), "r"(v) : "memory");
}
__device__ __forceinline__ void st_cluster_u64(unsigned laddr, unsigned rank, unsigned long long v) {
    unsigned pa;
    asm volatile("mapa.shared::cluster.u32 %0, %1, %2;" : "=r"(pa) : "r"(laddr), "r"(rank));
    asm volatile("st.shared::cluster.u64 [%0], %1;" :: "r"(pa), "l"(v) : "memory");
}
__device__ __forceinline__ void mbar_init(unsigned laddr, unsigned count) {
    asm volatile("mbarrier.init.shared.b64 [%0], %1;" :: "r"(laddr), "r"(count) : "memory");
}
__device__ __forceinline__ void mbar_arrive_cluster(unsigned laddr, unsigned rank) {
    unsigned pa;
    asm volatile("mapa.shared::cluster.u32 %0, %1, %2;" : "=r"(pa) : "r"(laddr), "r"(rank));
    asm volatile("mbarrier.arrive.release.cluster.shared::cluster.b64 _, [%0];" :: "r"(pa) : "memory");
}
__device__ __forceinline__ void mbar_wait_parity(unsigned laddr, unsigned parity) {
    asm volatile(
        "{\n\t.reg .pred P;\n\t"
        "WL_%=:\n\t"
        "mbarrier.try_wait.parity.acquire.cluster.shared::cta.b64 P, [%0], %1;\n\t"
        "@!P bra WL_%=;\n\t}"
        :: "r"(laddr), "r"(parity) : "memory");
}
#define CLUSTER_SYNC() do { \
    asm volatile("barrier.cluster.arrive.aligned;" ::: "memory"); \
    asm volatile("barrier.cluster.wait.aligned;" ::: "memory"); } while (0)

// ---------------- zero stats ----------------
__global__ void k_zero() {
    int t = blockIdx.x * blockDim.x + threadIdx.x;
    if (t < 6 * BB * 64) { g_sum[t] = 0.f; g_sq[t] = 0.f; }
}

// ---------------- transpose [B,3,N] -> [B,N,3] + copy pc to out ----------------
__global__ void k_transpose(const float* __restrict__ pc, const float* __restrict__ feat,
                            float* __restrict__ out_pc) {
    int i = blockIdx.x * blockDim.x + threadIdx.x;
    if (i < BB * 3 * N0) {
        int b = i / (3 * N0);
        int c = (i / N0) % 3;
        int n = i % N0;
        float v = pc[i];
        g_xyz0 [(b * N0 + n) * 3 + c] = v;
        g_feat0[(b * N0 + n) * 3 + c] = feat[i];
        out_pc[i] = v;
    }
}

// ---------------- farthest point sampling (cluster push + mbarrier; R10 structure) ----
// LOAD-BEARING for bit-compat with the XLA reference (do not alter):
//   * distance form rn(fma(dz,dz, fma(dy,dy, rn(dx*dx)))) with dx = rn(x + (-cx))
//   * exact GLOBAL max, then 1-ulp tie window with minimum-GLOBAL-index selection
// Candidate-filtered rescan (only warps within 1 ulp of block max) + shared atomics
// proved fastest (R10); T=256 shrinks barrier width/arrival spread.
template <int N, int S, int T, int C, int SEG>
__global__ void __launch_bounds__(T, 1)
k_fps(const float* __restrict__ xyz,
      float* __restrict__ sel_xyz,   // [b][s][3]
      float* __restrict__ out_pc,    // [b][3][S]
      float* __restrict__ out_fidx,  // [b][S] as float
      int i0, int i1)
{
    extern __shared__ float sm[];
    float* sx = sm;
    float* sy = sm + N;
    float* sz = sm + 2 * N;
    float4* sel = (float4*)(sm + 3 * N);       // SEG staged rows (x,y,z,idx)
    constexpr int NW = T / 32;
    constexpr int CS = (C > 1) ? C : 1;
    __shared__ unsigned swmax[NW];
    __shared__ int s_argA[2], s_argB[2];
    __shared__ unsigned long long s_mbar;
    __shared__ unsigned s_slotM[2][CS];
    __shared__ unsigned long long s_slotAB[2][CS];

    const int tid = threadIdx.x;
    const int lane = tid & 31;
    const int b = blockIdx.x / C;
    const int rank = blockIdx.x % C;
    constexpr int NL = N / C;        // points per CTA
    constexpr int PL = NL / T;       // points per thread
    constexpr int PAIRS = PL / 2;
    const int base = rank * NL;

    const float* xb = xyz + (size_t)b * N * 3;

    // full xyz copy (centroid lookup only)
    for (int p = tid; p < N; p += T) {
        sx[p] = xb[p * 3 + 0];
        sy[p] = xb[p * 3 + 1];
        sz[p] = xb[p * 3 + 2];
    }
    // register-resident slice
    unsigned long long X[PAIRS], Y[PAIRS], Z[PAIRS];
    float dist[PL];
#pragma unroll
    for (int jj = 0; jj < PAIRS; jj++) {
        int p0 = base + tid + jj * (2 * T);
        int p1 = p0 + T;
        X[jj] = pk2(xb[p0 * 3 + 0], xb[p1 * 3 + 0]);
        Y[jj] = pk2(xb[p0 * 3 + 1], xb[p1 * 3 + 1]);
        Z[jj] = pk2(xb[p0 * 3 + 2], xb[p1 * 3 + 2]);
        if (i0 == 0) { dist[2 * jj] = 1e10f; dist[2 * jj + 1] = 1e10f; }
        else { dist[2 * jj] = g_dist[b * N + p0]; dist[2 * jj + 1] = g_dist[b * N + p1]; }
    }
    int far = (i0 == 0) ? 0 : g_far[b];
    if (tid < 2) { s_argA[tid] = 0x7fffffff; s_argB[tid] = 0x7fffffff; }
    if (tid == 0 && C > 1) mbar_init(smem_u32addr(&s_mbar), C);
    __syncthreads();
    if constexpr (C > 1) CLUSTER_SYNC();   // all CTAs' mbarriers initialized

    const unsigned a_mbar   = smem_u32addr(&s_mbar);
    const unsigned a_slotM  = smem_u32addr(&s_slotM[0][0]);
    const unsigned a_slotAB = smem_u32addr(&s_slotAB[0][0]);

    int ph = 0;
    for (int i = i0; i < i1; i++) {
        const int par = ph;
        float cx = sx[far], cy = sy[far], cz = sz[far];   // broadcast LDS
        if (tid == 0) sel[i - i0] = make_float4(cx, cy, cz, (float)far);
        const unsigned long long ncx2 = pk2(-cx, -cx);
        const unsigned long long ncy2 = pk2(-cy, -cy);
        const unsigned long long ncz2 = pk2(-cz, -cz);
        float mval = 0.f;
#pragma unroll
        for (int jj = 0; jj < PAIRS; jj++) {
            unsigned long long dx = add2(X[jj], ncx2);
            unsigned long long dy = add2(Y[jj], ncy2);
            unsigned long long dz = add2(Z[jj], ncz2);
            unsigned long long t  = mul2(dx, dx);
            t = fma2(dy, dy, t);
            t = fma2(dz, dz, t);
            float da, db; upk2(t, da, db);
            float n0 = fminf(dist[2 * jj],     da);
            float n1 = fminf(dist[2 * jj + 1], db);
            dist[2 * jj]     = n0;
            dist[2 * jj + 1] = n1;
            mval = fmaxf(mval, fmaxf(n0, n1));
        }
        // warp max then block max (dist>=0 -> float bits monotone, max exact)
        unsigned wm = redux_max(__float_as_uint(mval));
        if (lane == 0) swmax[tid >> 5] = wm;
        __syncthreads();                                    // B1
        const unsigned lmax = redux_max(swmax[lane & (NW - 1)]);
        if (lmax - __float_as_uint(mval) <= 1u) {           // candidate threads rescan
#pragma unroll
            for (int j = 0; j < PL; j++) {
                unsigned db = __float_as_uint(dist[j]);
                unsigned diff = lmax - db;
                if (diff <= 1u) {
                    int p = tid + (j >> 1) * (2 * T) + (j & 1) * T;
                    if (diff == 0) atomicMin(&s_argA[par], p);
                    else           atomicMin(&s_argB[par], p);
                }
            }
        }
        __syncthreads();                                    // B2: argA/argB final
        if constexpr (C > 1) {
            if (tid < C) {   // lane r pushes this CTA's tuple to CTA r
                unsigned aA = (unsigned)s_argA[par];
                unsigned aB = (unsigned)s_argB[par];
                st_cluster_u32(a_slotM  + 4u * (par * C + rank), (unsigned)tid, lmax);
                st_cluster_u64(a_slotAB + 8u * (par * C + rank), (unsigned)tid,
                               ((unsigned long long)aA << 32) | aB);
                mbar_arrive_cluster(a_mbar, (unsigned)tid);  // release-orders the STs
            }
            if (tid == 32) { s_argA[par ^ 1] = 0x7fffffff; s_argB[par ^ 1] = 0x7fffffff; }
            mbar_wait_parity(a_mbar, par);                   // acquire
            // combine redundantly in every warp (no extra block barrier)
            unsigned mb = s_slotM[par][lane & (C - 1)];
            unsigned long long ab = s_slotAB[par][lane & (C - 1)];
            unsigned g = redux_max(mb);                      // exact global max
            unsigned cand = 0x7fffffffu;
            if (lane < C) {
                unsigned aA = (unsigned)(ab >> 32), aB = (unsigned)ab;
                if (mb == g)           cand = aA < aB ? aA : aB;  // both bins in window
                else if (g - mb == 1u) cand = aA;                 // only exact bin
                if (cand != 0x7fffffffu) cand += (unsigned)(lane * NL);
            }
            far = (int)redux_min(cand);                      // min global index
        } else {
            int aA = s_argA[par], aB = s_argB[par];
            far = aA < aB ? aA : aB;                         // min index within window
            if (tid == 32) { s_argA[par ^ 1] = 0x7fffffff; s_argB[par ^ 1] = 0x7fffffff; }
        }
        ph ^= 1;
    }

    if (i1 < S) {   // persist segment state
#pragma unroll
        for (int j = 0; j < PL; j++)
            g_dist[b * N + base + tid + (j >> 1) * (2 * T) + (j & 1) * T] = dist[j];
        if (rank == 0 && tid == 0) g_far[b] = far;
    }
    if (rank == 0) {    // bulk, coalesced output write for positions [i0, i1)
        for (int r = tid; r < i1 - i0; r += T) {
            float4 w = sel[r];
            int i = i0 + r;
            sel_xyz[((size_t)(b * S + i)) * 3 + 0] = w.x;
            sel_xyz[((size_t)(b * S + i)) * 3 + 1] = w.y;
            sel_xyz[((size_t)(b * S + i)) * 3 + 2] = w.z;
            out_pc[b * 3 * S + 0 * S + i] = w.x;
            out_pc[b * 3 * S + 1 * S + i] = w.y;
            out_pc[b * 3 * S + 2 * S + i] = w.z;
            out_fidx[b * S + i] = w.w;
        }
    }
    if constexpr (C > 1) CLUSTER_SYNC();   // exit safety: peers' smem stays live
}

// ---------------- kNN (k=32): warp-cooperative exact bitonic top-32 ----------------
__device__ __forceinline__ unsigned long long bitonic_sort32(unsigned long long v, int lane) {
#pragma unroll
    for (int k = 2; k <= 32; k <<= 1) {
#pragma unroll
        for (int j = k >> 1; j; j >>= 1) {
            unsigned long long o = __shfl_xor_sync(0xffffffffu, v, j);
            bool up    = (lane & k) == 0;
            bool lower = (lane & j) == 0;
            v = (lower == up) ? ullmin2(v, o) : ullmax2(v, o);
        }
    }
    return v;
}
__device__ __forceinline__ unsigned long long bitonic_merge32(unsigned long long v, int lane) {
#pragma unroll
    for (int j = 16; j; j >>= 1) {
        unsigned long long o = __shfl_xor_sync(0xffffffffu, v, j);
        v = ((lane & j) == 0) ? ullmin2(v, o) : ullmax2(v, o);
    }
    return v;
}

template <int N, int S, int CHUNK>
__global__ void k_knn(const float* __restrict__ q, const float* __restrict__ ref,
                      int* __restrict__ nidx, int q0, int nq)
{
    __shared__ float sref[CHUNK * 3];
    const int tid  = threadIdx.x;
    const int lane = tid & 31;
    const int warp = tid >> 5;
    const int per_b = nq / 8;
    const int b = blockIdx.x / per_b;
    const int s = q0 + (blockIdx.x % per_b) * 8 + warp;

    const float qx = q[(b * S + s) * 3 + 0];
    const float qy = q[(b * S + s) * 3 + 1];
    const float qz = q[(b * S + s) * 3 + 2];
    const float qq = fmaf(qz, qz, fmaf(qy, qy, __fmul_rn(qx, qx)));

    unsigned long long topv = ~0ull;
    unsigned long long thr  = ~0ull;

    const float* rb = ref + (size_t)b * N * 3;
    for (int ch = 0; ch < N; ch += CHUNK) {
        for (int i = tid; i < CHUNK * 3; i += 256) sref[i] = rb[ch * 3 + i];
        __syncthreads();
#pragma unroll 2
        for (int c = 0; c < CHUNK / 32; c++) {
            int il = c * 32 + lane;
            float rx = sref[il * 3 + 0];
            float ry = sref[il * 3 + 1];
            float rz = sref[il * 3 + 2];
            float dot = fmaf(qz, rz, fmaf(qy, ry, __fmul_rn(qx, rx)));
            float rr  = fmaf(rz, rz, fmaf(ry, ry, __fmul_rn(rx, rx)));
            float d = __fadd_rn(__fsub_rn(qq, __fmul_rn(2.f, dot)), rr);
            unsigned long long key = ((unsigned long long)fkey(d) << 32) | (unsigned)(ch + il);
            if (__ballot_sync(0xffffffffu, key < thr)) {
                unsigned long long v = bitonic_sort32(key, lane);
                unsigned long long w = __shfl_xor_sync(0xffffffffu, v, 31);
                topv = bitonic_merge32(ullmin2(topv, w), lane);
                thr = __shfl_sync(0xffffffffu, topv, 31);
            }
        }
        __syncthreads();
    }
    nidx[((size_t)(b * S + s)) * KK + lane] = (int)(unsigned)(topv & 0xffffffffu);
}

// ---------------- gather + first 1x1 conv + stats (chunkable over s) ----------------
template <int FDIM, int COUT, int SS, int NREF>
__global__ void k_gather_mm(const float* __restrict__ refxyz,
                            const float* __restrict__ reffeat,
                            const float* __restrict__ newxyz,
                            const int* __restrict__ nidx,
                            const float* __restrict__ W,
                            float* __restrict__ y,
                            float* __restrict__ sum, float* __restrict__ sq,
                            int q0, int nq)
{
    constexpr int CIN = 3 + FDIM;
    __shared__ float sW[CIN * COUT];
    for (int i = threadIdx.x; i < CIN * COUT; i += blockDim.x) sW[i] = W[i];
    __syncthreads();

    int r0 = blockIdx.x * blockDim.x + threadIdx.x;
    int per_b = nq * KK;
    int b = r0 / per_b;
    int rem = q0 * KK + (r0 - b * per_b);
    int s = rem / KK;
    int n = nidx[(size_t)b * (SS * KK) + rem];

    float in[CIN];
#pragma unroll
    for (int c = 0; c < 3; c++)
        in[c] = refxyz[((size_t)(b * NREF + n)) * 3 + c] - newxyz[((size_t)(b * SS + s)) * 3 + c];
#pragma unroll
    for (int j = 0; j < FDIM; j++)
        in[3 + j] = reffeat[((size_t)(b * NREF + n)) * FDIM + j];

    float acc[COUT];
#pragma unroll
    for (int c = 0; c < COUT; c++) acc[c] = 0.f;
#pragma unroll
    for (int j = 0; j < CIN; j++) {
        float v = in[j];
#pragma unroll
        for (int c = 0; c < COUT; c++) acc[c] = fmaf(v, sW[j * COUT + c], acc[c]);
    }
#pragma unroll
    for (int c = 0; c < COUT; c++)
        y[((size_t)(b * COUT + c)) * (SS * KK) + rem] = acc[c];

    int lane = threadIdx.x & 31;
#pragma unroll
    for (int c = 0; c < COUT; c++) {
        float v = acc[c], v2 = v * v;
#pragma unroll
        for (int o = 16; o; o >>= 1) {
            v  += __shfl_down_sync(0xffffffffu, v,  o);
            v2 += __shfl_down_sync(0xffffffffu, v2, o);
        }
        if (lane == 0) { atomicAdd(&sum[b * 64 + c], v); atomicAdd(&sq[b * 64 + c], v2); }
    }
}

// ---------------- instance-norm + relu + 1x1 conv + stats ----------------
template <int CIN, int COUT, int SS>
__global__ void k_mm(const float* __restrict__ x, const float* __restrict__ W,
                     const float* __restrict__ sumIn, const float* __restrict__ sqIn,
                     float* __restrict__ y,
                     float* __restrict__ sumOut, float* __restrict__ sqOut)
{
    __shared__ float sW[CIN * COUT];
    __shared__ float sMu[CIN], sInv[CIN];
    int r = blockIdx.x * blockDim.x + threadIdx.x;
    int b = r / (SS * KK);
    int rem = r - b * (SS * KK);
    for (int i = threadIdx.x; i < CIN * COUT; i += blockDim.x) sW[i] = W[i];
    if (threadIdx.x < CIN) {
        float cnt = (float)(SS * KK);
        float mu = sumIn[b * 64 + threadIdx.x] / cnt;
        float var = sqIn[b * 64 + threadIdx.x] / cnt - mu * mu;
        sMu[threadIdx.x] = mu;
        sInv[threadIdx.x] = rsqrtf(var + 1e-5f);
    }
    __syncthreads();

    float acc[COUT];
#pragma unroll
    for (int c = 0; c < COUT; c++) acc[c] = 0.f;
#pragma unroll
    for (int j = 0; j < CIN; j++) {
        float v = x[((size_t)(b * CIN + j)) * (SS * KK) + rem];
        v = fmaxf(0.f, (v - sMu[j]) * sInv[j]);
#pragma unroll
        for (int c = 0; c < COUT; c++) acc[c] = fmaf(v, sW[j * COUT + c], acc[c]);
    }
#pragma unroll
    for (int c = 0; c < COUT; c++)
        y[((size_t)(b * COUT + c)) * (SS * KK) + rem] = acc[c];

    int lane = threadIdx.x & 31;
#pragma unroll
    for (int c = 0; c < COUT; c++) {
        float v = acc[c], v2 = v * v;
#pragma unroll
        for (int o = 16; o; o >>= 1) {
            v  += __shfl_down_sync(0xffffffffu, v,  o);
            v2 += __shfl_down_sync(0xffffffffu, v2, o);
        }
        if (lane == 0) { atomicAdd(&sumOut[b * 64 + c], v); atomicAdd(&sqOut[b * 64 + c], v2); }
    }
}

// ---------------- instance-norm + relu + maxpool over K ----------------
template <int C, int SS, bool CHMAJOR>
__global__ void k_maxpool(const float* __restrict__ x,
                          const float* __restrict__ sumIn, const float* __restrict__ sqIn,
                          float* __restrict__ outp)
{
    int t = blockIdx.x * blockDim.x + threadIdx.x;
    int s = t % SS;
    int c = (t / SS) % C;
    int b = t / (SS * C);
    float cnt = (float)(SS * KK);
    float mu = sumIn[b * 64 + c] / cnt;
    float var = sqIn[b * 64 + c] / cnt - mu * mu;
    float inv = rsqrtf(var + 1e-5f);

    const float4* p = reinterpret_cast<const float4*>(
        x + ((size_t)(b * C + c)) * (SS * KK) + (size_t)s * KK);
    float m = -3.4e38f;
#pragma unroll
    for (int qv = 0; qv < KK / 4; qv++) {
        float4 v = p[qv];
        m = fmaxf(m, fmaxf(fmaxf(v.x, v.y), fmaxf(v.z, v.w)));
    }
    float outv = fmaxf(0.f, (m - mu) * inv);
    if (CHMAJOR) outp[(b * C + c) * SS + s] = outv;
    else         outp[(b * SS + s) * C + c] = outv;
}

// ---------------- launch ----------------
extern "C" void kernel_launch(void* const* d_in, const int* in_sizes, int n_in,
                              void* d_out, int out_size)
{
    const float* pc     = (const float*)d_in[0];
    const float* feat   = (const float*)d_in[1];
    const float* sa1_w1 = (const float*)d_in[2];
    const float* sa1_w2 = (const float*)d_in[3];
    const float* sa1_w3 = (const float*)d_in[4];
    const float* sa2_w1 = (const float*)d_in[5];
    const float* sa2_w2 = (const float*)d_in[6];
    const float* sa2_w3 = (const float*)d_in[7];

    float* out = (float*)d_out;
    float* out_pc      = out;
    float* out_pc_l1   = out + 196608;
    float* out_pc_l2   = out + 196608 + 24576;
    float* out_feat_l2 = out + 196608 + 24576 + 12288;
    float* out_fidx1   = out + 196608 + 24576 + 12288 + 262144;
    float* out_fidx2   = out + 196608 + 24576 + 12288 + 262144 + 8192;

    float *xyz0, *feat0, *xyz1, *xyz2, *feat1, *bufA, *bufB, *sum, *sq;
    int *nidx1, *nidx2;
    cudaGetSymbolAddress((void**)&xyz0,  g_xyz0);
    cudaGetSymbolAddress((void**)&feat0, g_feat0);
    cudaGetSymbolAddress((void**)&xyz1,  g_xyz1);
    cudaGetSymbolAddress((void**)&xyz2,  g_xyz2);
    cudaGetSymbolAddress((void**)&feat1, g_feat1);
    cudaGetSymbolAddress((void**)&bufA,  g_bufA);
    cudaGetSymbolAddress((void**)&bufB,  g_bufB);
    cudaGetSymbolAddress((void**)&sum,   g_sum);
    cudaGetSymbolAddress((void**)&sq,    g_sq);
    cudaGetSymbolAddress((void**)&nidx1, g_nidx1);
    cudaGetSymbolAddress((void**)&nidx2, g_nidx2);

    constexpr int CL = 8;                            // cluster size for stage-1 FPS
    constexpr int SMEM1 = 3 * N0 * 4 + 512 * 16;     // full xyz copy + staged rows = 200KB
    constexpr int SMEM2 = 3 * S1V * 4 + 512 * 16;    // 24KB + 8KB = 32KB
    cudaFuncSetAttribute((const void*)k_fps<N0, S1V, 256, CL, 512>,
                         cudaFuncAttributeMaxDynamicSharedMemorySize, SMEM1);
    cudaFuncSetAttribute((const void*)k_fps<S1V, S2V, 256, 1, 512>,
                         cudaFuncAttributeMaxDynamicSharedMemorySize, SMEM2);

    // one-time side streams + events (host objects only; no device allocation)
    static cudaStream_t s1 = nullptr, s2 = nullptr;
    static cudaEvent_t evSeg[4], evPool1, evF2[2], evK2;
    if (!s1) {
        cudaStreamCreateWithFlags(&s1, cudaStreamNonBlocking);
        cudaStreamCreateWithFlags(&s2, cudaStreamNonBlocking);
        for (int i = 0; i < 4; i++) cudaEventCreateWithFlags(&evSeg[i], cudaEventDisableTiming);
        cudaEventCreateWithFlags(&evPool1, cudaEventDisableTiming);
        for (int i = 0; i < 2; i++) cudaEventCreateWithFlags(&evF2[i], cudaEventDisableTiming);
        cudaEventCreateWithFlags(&evK2, cudaEventDisableTiming);
    }

    k_zero<<<6, 256>>>();
    k_transpose<<<768, 256>>>(pc, feat, out_pc);

    // ---- FPS1: 4 cluster-parallel segments on main stream; kNN1/gather1 trail on s1 ----
    for (int seg = 0; seg < 4; seg++) {
        cudaLaunchConfig_t cfg = {};
        cfg.gridDim = dim3(BB * CL, 1, 1);
        cfg.blockDim = dim3(256, 1, 1);
        cfg.dynamicSmemBytes = SMEM1;
        cfg.stream = 0;
        cudaLaunchAttribute attrs[1];
        attrs[0].id = cudaLaunchAttributeClusterDimension;
        attrs[0].val.clusterDim.x = CL;
        attrs[0].val.clusterDim.y = 1;
        attrs[0].val.clusterDim.z = 1;
        cfg.attrs = attrs;
        cfg.numAttrs = 1;
        cudaLaunchKernelEx(&cfg, k_fps<N0, S1V, 256, CL, 512>,
                           (const float*)xyz0, xyz1, out_pc_l1, out_fidx1,
                           seg * 512, (seg + 1) * 512);
        cudaEventRecord(evSeg[seg], 0);
    }
    for (int seg = 0; seg < 4; seg++) {
        cudaStreamWaitEvent(s1, evSeg[seg], 0);
        k_knn<N0, S1V, 2048><<<BB * 512 / 8, 256, 0, s1>>>(xyz1, xyz0, nidx1, seg * 512, 512);
        k_gather_mm<3, 32, S1V, N0><<<(BB * 512 * KK) / 256, 256, 0, s1>>>(
            xyz0, feat0, xyz1, nidx1, sa1_w1, bufA,
            sum + 0 * BB * 64, sq + 0 * BB * 64, seg * 512, 512);
    }
    // stage-1 MLP tail on s1
    k_mm<32, 32, S1V><<<(BB * S1V * KK) / 256, 256, 0, s1>>>(
        bufA, sa1_w2, sum + 0 * BB * 64, sq + 0 * BB * 64, bufB,
        sum + 1 * BB * 64, sq + 1 * BB * 64);
    k_mm<32, 32, S1V><<<(BB * S1V * KK) / 256, 256, 0, s1>>>(
        bufB, sa1_w3, sum + 1 * BB * 64, sq + 1 * BB * 64, bufA,
        sum + 2 * BB * 64, sq + 2 * BB * 64);
    k_maxpool<32, S1V, false><<<(BB * 32 * S1V) / 256, 256, 0, s1>>>(
        bufA, sum + 2 * BB * 64, sq + 2 * BB * 64, feat1);
    cudaEventRecord(evPool1, s1);

    // ---- FPS2 (C=1) in 2 segments on main; kNN2 chunks trail on s2 ----
    k_fps<S1V, S2V, 256, 1, 512><<<BB, 256, SMEM2>>>(
        xyz1, xyz2, out_pc_l2, out_fidx2, 0, 512);
    cudaEventRecord(evF2[0], 0);
    k_fps<S1V, S2V, 256, 1, 512><<<BB, 256, SMEM2>>>(
        xyz1, xyz2, out_pc_l2, out_fidx2, 512, S2V);
    cudaEventRecord(evF2[1], 0);
    cudaStreamWaitEvent(s2, evF2[0], 0);
    k_knn<S1V, S2V, 2048><<<BB * 512 / 8, 256, 0, s2>>>(xyz2, xyz1, nidx2, 0, 512);
    cudaStreamWaitEvent(s2, evF2[1], 0);
    k_knn<S1V, S2V, 2048><<<BB * 512 / 8, 256, 0, s2>>>(xyz2, xyz1, nidx2, 512, 512);
    cudaEventRecord(evK2, s2);

    // ---- join, then stage-2 MLP on main stream ----
    cudaStreamWaitEvent(0, evPool1, 0);
    cudaStreamWaitEvent(0, evK2, 0);
    k_gather_mm<32, 64, S2V, S1V><<<(BB * S2V * KK) / 256, 256>>>(
        xyz1, feat1, xyz2, nidx2, sa2_w1, bufA,
        sum + 3 * BB * 64, sq + 3 * BB * 64, 0, S2V);
    k_mm<64, 64, S2V><<<(BB * S2V * KK) / 256, 256>>>(
        bufA, sa2_w2, sum + 3 * BB * 64, sq + 3 * BB * 64, bufB,
        sum + 4 * BB * 64, sq + 4 * BB * 64);
    k_mm<64, 64, S2V><<<(BB * S2V * KK) / 256, 256>>>(
        bufB, sa2_w3, sum + 4 * BB * 64, sq + 4 * BB * 64, bufA,
        sum + 5 * BB * 64, sq + 5 * BB * 64);
    k_maxpool<64, S2V, true><<<(BB * 64 * S2V) / 256, 256>>>(
        bufA, sum + 5 * BB * 64, sq + 5 * BB * 64, out_feat_l2);
}

// round 13
// speedup vs baseline: 1.0306x; 1.0306x over previous
#include <cuda_runtime.h>
#include <cstdint>

#define BB  4
#define N0  16384
#define S1V 2048
#define S2V 1024
#define KK  32

// ---------------- device scratch (no allocations allowed) ----------------
__device__ __align__(16) float g_xyz0 [BB * N0  * 3];
__device__ __align__(16) float g_feat0[BB * N0  * 3];
__device__ __align__(16) float g_xyz1 [BB * S1V * 3];
__device__ __align__(16) float g_xyz2 [BB * S2V * 3];
__device__ int   g_nidx1[BB * S1V * KK];
__device__ int   g_nidx2[BB * S2V * KK];
__device__ __align__(16) float g_feat1[BB * S1V * 32];
__device__ __align__(16) float g_bufA [8388608];   // [b][c][s*K+k] channel-major
__device__ __align__(16) float g_bufB [8388608];
__device__ float g_sum[6 * BB * 64];
__device__ float g_sq [6 * BB * 64];
__device__ __align__(16) float g_dist[BB * N0];    // FPS segment-persisted min-dist
__device__ int   g_far[BB];

// ---------------- helpers ----------------
__device__ __forceinline__ unsigned fkey(float f) {
    unsigned u = __float_as_uint(f);
    return u ^ (((unsigned)((int)u >> 31)) | 0x80000000u);
}
__device__ __forceinline__ unsigned long long ullmin2(unsigned long long a, unsigned long long b){return a<b?a:b;}
__device__ __forceinline__ unsigned long long ullmax2(unsigned long long a, unsigned long long b){return a>b?a:b;}

// packed f32x2 ops (Blackwell). Per-lane rounding identical to scalar rn.
__device__ __forceinline__ unsigned long long pk2(float a, float b) {
    unsigned long long r; asm("mov.b64 %0, {%1, %2};" : "=l"(r) : "f"(a), "f"(b)); return r;
}
__device__ __forceinline__ void upk2(unsigned long long v, float& a, float& b) {
    asm("mov.b64 {%0, %1}, %2;" : "=f"(a), "=f"(b) : "l"(v));
}
__device__ __forceinline__ unsigned long long add2(unsigned long long a, unsigned long long b) {
    unsigned long long r; asm("add.rn.f32x2 %0, %1, %2;" : "=l"(r) : "l"(a), "l"(b)); return r;
}
__device__ __forceinline__ unsigned long long mul2(unsigned long long a, unsigned long long b) {
    unsigned long long r; asm("mul.rn.f32x2 %0, %1, %2;" : "=l"(r) : "l"(a), "l"(b)); return r;
}
__device__ __forceinline__ unsigned long long fma2(unsigned long long a, unsigned long long b, unsigned long long c) {
    unsigned long long r; asm("fma.rn.f32x2 %0, %1, %2, %3;" : "=l"(r) : "l"(a), "l"(b), "l"(c)); return r;
}

// warp-uniform reductions (sm_80+)
__device__ __forceinline__ unsigned redux_max(unsigned v) {
    unsigned r; asm volatile("redux.sync.max.u32 %0, %1, 0xffffffff;" : "=r"(r) : "r"(v)); return r;
}
__device__ __forceinline__ unsigned redux_min(unsigned v) {
    unsigned r; asm volatile("redux.sync.min.u32 %0, %1, 0xffffffff;" : "=r"(r) : "r"(v)); return r;
}

// shared-address + cluster comm helpers
__device__ __forceinline__ unsigned smem_u32addr(const void* p) {
    unsigned r;
    asm("{ .reg .u64 t; cvta.to.shared.u64 t, %1; cvt.u32.u64 %0, t; }" : "=r"(r) : "l"(p));
    return r;
}
__device__ __forceinline__ void st_cluster_u32(unsigned laddr, unsigned rank, unsigned v) {
    unsigned pa;
    asm volatile("mapa.shared::cluster.u32 %0, %1, %2;" : "=r"(pa) : "r"(laddr), "r"(rank));
    asm volatile("st.shared::cluster.u32 [%0], %1;" :: "r"(pa), "r"(v) : "memory");
}
__device__ __forceinline__ void st_cluster_u64(unsigned laddr, unsigned rank, unsigned long long v) {
    unsigned pa;
    asm volatile("mapa.shared::cluster.u32 %0, %1, %2;" : "=r"(pa) : "r"(laddr), "r"(rank));
    asm volatile("st.shared::cluster.u64 [%0], %1;" :: "r"(pa), "l"(v) : "memory");
}
__device__ __forceinline__ void mbar_init(unsigned laddr, unsigned count) {
    asm volatile("mbarrier.init.shared.b64 [%0], %1;" :: "r"(laddr), "r"(count) : "memory");
}
__device__ __forceinline__ void mbar_arrive_cluster(unsigned laddr, unsigned rank) {
    unsigned pa;
    asm volatile("mapa.shared::cluster.u32 %0, %1, %2;" : "=r"(pa) : "r"(laddr), "r"(rank));
    asm volatile("mbarrier.arrive.release.cluster.shared::cluster.b64 _, [%0];" :: "r"(pa) : "memory");
}
__device__ __forceinline__ void mbar_wait_parity(unsigned laddr, unsigned parity) {
    asm volatile(
        "{\n\t.reg .pred P;\n\t"
        "WL_%=:\n\t"
        "mbarrier.try_wait.parity.acquire.cluster.shared::cta.b64 P, [%0], %1;\n\t"
        "@!P bra WL_%=;\n\t}"
        :: "r"(laddr), "r"(parity) : "memory");
}
#define CLUSTER_SYNC() do { \
    asm volatile("barrier.cluster.arrive.aligned;" ::: "memory"); \
    asm volatile("barrier.cluster.wait.aligned;" ::: "memory"); } while (0)

// ---------------- zero stats ----------------
__global__ void k_zero() {
    int t = blockIdx.x * blockDim.x + threadIdx.x;
    if (t < 6 * BB * 64) { g_sum[t] = 0.f; g_sq[t] = 0.f; }
}

// ---------------- transpose [B,3,N] -> [B,N,3] + copy pc to out ----------------
__global__ void k_transpose(const float* __restrict__ pc, const float* __restrict__ feat,
                            float* __restrict__ out_pc) {
    int i = blockIdx.x * blockDim.x + threadIdx.x;
    if (i < BB * 3 * N0) {
        int b = i / (3 * N0);
        int c = (i / N0) % 3;
        int n = i % N0;
        float v = pc[i];
        g_xyz0 [(b * N0 + n) * 3 + c] = v;
        g_feat0[(b * N0 + n) * 3 + c] = feat[i];
        out_pc[i] = v;
    }
}

// ---------------- farthest point sampling (cluster push + mbarrier; R10 structure) ----
// LOAD-BEARING for bit-compat with the XLA reference (do not alter):
//   * distance form rn(fma(dz,dz, fma(dy,dy, rn(dx*dx)))) with dx = rn(x + (-cx))
//   * exact GLOBAL max, then 1-ulp tie window with minimum-GLOBAL-index selection
template <int N, int S, int T, int C, int SEG>
__global__ void __launch_bounds__(T, 1)
k_fps(const float* __restrict__ xyz,
      float* __restrict__ sel_xyz,   // [b][s][3]
      float* __restrict__ out_pc,    // [b][3][S]
      float* __restrict__ out_fidx,  // [b][S] as float
      int i0, int i1)
{
    extern __shared__ float sm[];
    float* sx = sm;
    float* sy = sm + N;
    float* sz = sm + 2 * N;
    float4* sel = (float4*)(sm + 3 * N);       // SEG staged rows (x,y,z,idx)
    constexpr int NW = T / 32;
    constexpr int CS = (C > 1) ? C : 1;
    __shared__ unsigned swmax[NW];
    __shared__ int s_argA[2], s_argB[2];
    __shared__ unsigned long long s_mbar;
    __shared__ unsigned s_slotM[2][CS];
    __shared__ unsigned long long s_slotAB[2][CS];

    const int tid = threadIdx.x;
    const int lane = tid & 31;
    const int b = blockIdx.x / C;
    const int rank = blockIdx.x % C;
    constexpr int NL = N / C;        // points per CTA
    constexpr int PL = NL / T;       // points per thread
    constexpr int PAIRS = PL / 2;
    const int base = rank * NL;

    const float* xb = xyz + (size_t)b * N * 3;

    // full xyz copy (centroid lookup only)
    for (int p = tid; p < N; p += T) {
        sx[p] = xb[p * 3 + 0];
        sy[p] = xb[p * 3 + 1];
        sz[p] = xb[p * 3 + 2];
    }
    // register-resident slice
    unsigned long long X[PAIRS], Y[PAIRS], Z[PAIRS];
    float dist[PL];
#pragma unroll
    for (int jj = 0; jj < PAIRS; jj++) {
        int p0 = base + tid + jj * (2 * T);
        int p1 = p0 + T;
        X[jj] = pk2(xb[p0 * 3 + 0], xb[p1 * 3 + 0]);
        Y[jj] = pk2(xb[p0 * 3 + 1], xb[p1 * 3 + 1]);
        Z[jj] = pk2(xb[p0 * 3 + 2], xb[p1 * 3 + 2]);
        if (i0 == 0) { dist[2 * jj] = 1e10f; dist[2 * jj + 1] = 1e10f; }
        else { dist[2 * jj] = g_dist[b * N + p0]; dist[2 * jj + 1] = g_dist[b * N + p1]; }
    }
    int far = (i0 == 0) ? 0 : g_far[b];
    if (tid < 2) { s_argA[tid] = 0x7fffffff; s_argB[tid] = 0x7fffffff; }
    if (tid == 0 && C > 1) mbar_init(smem_u32addr(&s_mbar), C);
    __syncthreads();
    if constexpr (C > 1) CLUSTER_SYNC();   // all CTAs' mbarriers initialized

    const unsigned a_mbar   = smem_u32addr(&s_mbar);
    const unsigned a_slotM  = smem_u32addr(&s_slotM[0][0]);
    const unsigned a_slotAB = smem_u32addr(&s_slotAB[0][0]);

    int ph = 0;
    for (int i = i0; i < i1; i++) {
        const int par = ph;
        float cx = sx[far], cy = sy[far], cz = sz[far];   // broadcast LDS
        if (tid == 0) sel[i - i0] = make_float4(cx, cy, cz, (float)far);
        const unsigned long long ncx2 = pk2(-cx, -cx);
        const unsigned long long ncy2 = pk2(-cy, -cy);
        const unsigned long long ncz2 = pk2(-cz, -cz);
        float mval = 0.f;
#pragma unroll
        for (int jj = 0; jj < PAIRS; jj++) {
            unsigned long long dx = add2(X[jj], ncx2);
            unsigned long long dy = add2(Y[jj], ncy2);
            unsigned long long dz = add2(Z[jj], ncz2);
            unsigned long long t  = mul2(dx, dx);
            t = fma2(dy, dy, t);
            t = fma2(dz, dz, t);
            float da, db; upk2(t, da, db);
            float n0 = fminf(dist[2 * jj],     da);
            float n1 = fminf(dist[2 * jj + 1], db);
            dist[2 * jj]     = n0;
            dist[2 * jj + 1] = n1;
            mval = fmaxf(mval, fmaxf(n0, n1));
        }
        // warp max then block max (dist>=0 -> float bits monotone, max exact)
        unsigned wm = redux_max(__float_as_uint(mval));
        if (lane == 0) swmax[tid >> 5] = wm;
        __syncthreads();                                    // B1
        const unsigned lmax = redux_max(swmax[lane & (NW - 1)]);
        if (lmax - __float_as_uint(mval) <= 1u) {           // candidate threads rescan
#pragma unroll
            for (int j = 0; j < PL; j++) {
                unsigned db = __float_as_uint(dist[j]);
                unsigned diff = lmax - db;
                if (diff <= 1u) {
                    int p = tid + (j >> 1) * (2 * T) + (j & 1) * T;
                    if (diff == 0) atomicMin(&s_argA[par], p);
                    else           atomicMin(&s_argB[par], p);
                }
            }
        }
        __syncthreads();                                    // B2: argA/argB final
        if constexpr (C > 1) {
            if (tid < C) {   // lane r pushes this CTA's tuple to CTA r
                unsigned aA = (unsigned)s_argA[par];
                unsigned aB = (unsigned)s_argB[par];
                st_cluster_u32(a_slotM  + 4u * (par * C + rank), (unsigned)tid, lmax);
                st_cluster_u64(a_slotAB + 8u * (par * C + rank), (unsigned)tid,
                               ((unsigned long long)aA << 32) | aB);
                mbar_arrive_cluster(a_mbar, (unsigned)tid);  // release-orders the STs
            }
            if (tid == 32) { s_argA[par ^ 1] = 0x7fffffff; s_argB[par ^ 1] = 0x7fffffff; }
            mbar_wait_parity(a_mbar, par);                   // acquire
            // combine redundantly in every warp (no extra block barrier)
            unsigned mb = s_slotM[par][lane & (C - 1)];
            unsigned long long ab = s_slotAB[par][lane & (C - 1)];
            unsigned g = redux_max(mb);                      // exact global max
            unsigned cand = 0x7fffffffu;
            if (lane < C) {
                unsigned aA = (unsigned)(ab >> 32), aB = (unsigned)ab;
                if (mb == g)           cand = aA < aB ? aA : aB;  // both bins in window
                else if (g - mb == 1u) cand = aA;                 // only exact bin
                if (cand != 0x7fffffffu) cand += (unsigned)(lane * NL);
            }
            far = (int)redux_min(cand);                      // min global index
        } else {
            int aA = s_argA[par], aB = s_argB[par];
            far = aA < aB ? aA : aB;                         // min index within window
            if (tid == 32) { s_argA[par ^ 1] = 0x7fffffff; s_argB[par ^ 1] = 0x7fffffff; }
        }
        ph ^= 1;
    }

    if (i1 < S) {   // persist segment state
#pragma unroll
        for (int j = 0; j < PL; j++)
            g_dist[b * N + base + tid + (j >> 1) * (2 * T) + (j & 1) * T] = dist[j];
        if (rank == 0 && tid == 0) g_far[b] = far;
    }
    if (rank == 0) {    // bulk, coalesced output write for positions [i0, i1)
        for (int r = tid; r < i1 - i0; r += T) {
            float4 w = sel[r];
            int i = i0 + r;
            sel_xyz[((size_t)(b * S + i)) * 3 + 0] = w.x;
            sel_xyz[((size_t)(b * S + i)) * 3 + 1] = w.y;
            sel_xyz[((size_t)(b * S + i)) * 3 + 2] = w.z;
            out_pc[b * 3 * S + 0 * S + i] = w.x;
            out_pc[b * 3 * S + 1 * S + i] = w.y;
            out_pc[b * 3 * S + 2 * S + i] = w.z;
            out_fidx[b * S + i] = w.w;
        }
    }
    if constexpr (C > 1) CLUSTER_SYNC();   // exit safety: peers' smem stays live
}

// ---------------- kNN (k=32): warp-cooperative exact bitonic top-32 ----------------
__device__ __forceinline__ unsigned long long bitonic_sort32(unsigned long long v, int lane) {
#pragma unroll
    for (int k = 2; k <= 32; k <<= 1) {
#pragma unroll
        for (int j = k >> 1; j; j >>= 1) {
            unsigned long long o = __shfl_xor_sync(0xffffffffu, v, j);
            bool up    = (lane & k) == 0;
            bool lower = (lane & j) == 0;
            v = (lower == up) ? ullmin2(v, o) : ullmax2(v, o);
        }
    }
    return v;
}
__device__ __forceinline__ unsigned long long bitonic_merge32(unsigned long long v, int lane) {
#pragma unroll
    for (int j = 16; j; j >>= 1) {
        unsigned long long o = __shfl_xor_sync(0xffffffffu, v, j);
        v = ((lane & j) == 0) ? ullmin2(v, o) : ullmax2(v, o);
    }
    return v;
}

template <int N, int S, int CHUNK>
__global__ void k_knn(const float* __restrict__ q, const float* __restrict__ ref,
                      int* __restrict__ nidx, int q0, int nq)
{
    __shared__ float sref[CHUNK * 3];
    const int tid  = threadIdx.x;
    const int lane = tid & 31;
    const int warp = tid >> 5;
    const int per_b = nq / 8;
    const int b = blockIdx.x / per_b;
    const int s = q0 + (blockIdx.x % per_b) * 8 + warp;

    const float qx = q[(b * S + s) * 3 + 0];
    const float qy = q[(b * S + s) * 3 + 1];
    const float qz = q[(b * S + s) * 3 + 2];
    const float qq = fmaf(qz, qz, fmaf(qy, qy, __fmul_rn(qx, qx)));

    unsigned long long topv = ~0ull;
    unsigned long long thr  = ~0ull;

    const float* rb = ref + (size_t)b * N * 3;
    for (int ch = 0; ch < N; ch += CHUNK) {
        for (int i = tid; i < CHUNK * 3; i += 256) sref[i] = rb[ch * 3 + i];
        __syncthreads();
#pragma unroll 2
        for (int c = 0; c < CHUNK / 32; c++) {
            int il = c * 32 + lane;
            float rx = sref[il * 3 + 0];
            float ry = sref[il * 3 + 1];
            float rz = sref[il * 3 + 2];
            float dot = fmaf(qz, rz, fmaf(qy, ry, __fmul_rn(qx, rx)));
            float rr  = fmaf(rz, rz, fmaf(ry, ry, __fmul_rn(rx, rx)));
            float d = __fadd_rn(__fsub_rn(qq, __fmul_rn(2.f, dot)), rr);
            unsigned long long key = ((unsigned long long)fkey(d) << 32) | (unsigned)(ch + il);
            if (__ballot_sync(0xffffffffu, key < thr)) {
                unsigned long long v = bitonic_sort32(key, lane);
                unsigned long long w = __shfl_xor_sync(0xffffffffu, v, 31);
                topv = bitonic_merge32(ullmin2(topv, w), lane);
                thr = __shfl_sync(0xffffffffu, topv, 31);
            }
        }
        __syncthreads();
    }
    nidx[((size_t)(b * S + s)) * KK + lane] = (int)(unsigned)(topv & 0xffffffffu);
}

// ---------------- gather + first 1x1 conv + stats (chunkable over s) ----------------
template <int FDIM, int COUT, int SS, int NREF>
__global__ void k_gather_mm(const float* __restrict__ refxyz,
                            const float* __restrict__ reffeat,
                            const float* __restrict__ newxyz,
                            const int* __restrict__ nidx,
                            const float* __restrict__ W,
                            float* __restrict__ y,
                            float* __restrict__ sum, float* __restrict__ sq,
                            int q0, int nq)
{
    constexpr int CIN = 3 + FDIM;
    __shared__ float sW[CIN * COUT];
    for (int i = threadIdx.x; i < CIN * COUT; i += blockDim.x) sW[i] = W[i];
    __syncthreads();

    int r0 = blockIdx.x * blockDim.x + threadIdx.x;
    int per_b = nq * KK;
    int b = r0 / per_b;
    int rem = q0 * KK + (r0 - b * per_b);
    int s = rem / KK;
    int n = nidx[(size_t)b * (SS * KK) + rem];

    float in[CIN];
#pragma unroll
    for (int c = 0; c < 3; c++)
        in[c] = refxyz[((size_t)(b * NREF + n)) * 3 + c] - newxyz[((size_t)(b * SS + s)) * 3 + c];
#pragma unroll
    for (int j = 0; j < FDIM; j++)
        in[3 + j] = reffeat[((size_t)(b * NREF + n)) * FDIM + j];

    float acc[COUT];
#pragma unroll
    for (int c = 0; c < COUT; c++) acc[c] = 0.f;
#pragma unroll
    for (int j = 0; j < CIN; j++) {
        float v = in[j];
#pragma unroll
        for (int c = 0; c < COUT; c++) acc[c] = fmaf(v, sW[j * COUT + c], acc[c]);
    }
#pragma unroll
    for (int c = 0; c < COUT; c++)
        y[((size_t)(b * COUT + c)) * (SS * KK) + rem] = acc[c];

    int lane = threadIdx.x & 31;
#pragma unroll
    for (int c = 0; c < COUT; c++) {
        float v = acc[c], v2 = v * v;
#pragma unroll
        for (int o = 16; o; o >>= 1) {
            v  += __shfl_down_sync(0xffffffffu, v,  o);
            v2 += __shfl_down_sync(0xffffffffu, v2, o);
        }
        if (lane == 0) { atomicAdd(&sum[b * 64 + c], v); atomicAdd(&sq[b * 64 + c], v2); }
    }
}

// ---------------- instance-norm + relu + 1x1 conv + stats ----------------
template <int CIN, int COUT, int SS>
__global__ void k_mm(const float* __restrict__ x, const float* __restrict__ W,
                     const float* __restrict__ sumIn, const float* __restrict__ sqIn,
                     float* __restrict__ y,
                     float* __restrict__ sumOut, float* __restrict__ sqOut)
{
    __shared__ float sW[CIN * COUT];
    __shared__ float sMu[CIN], sInv[CIN];
    int r = blockIdx.x * blockDim.x + threadIdx.x;
    int b = r / (SS * KK);
    int rem = r - b * (SS * KK);
    for (int i = threadIdx.x; i < CIN * COUT; i += blockDim.x) sW[i] = W[i];
    if (threadIdx.x < CIN) {
        float cnt = (float)(SS * KK);
        float mu = sumIn[b * 64 + threadIdx.x] / cnt;
        float var = sqIn[b * 64 + threadIdx.x] / cnt - mu * mu;
        sMu[threadIdx.x] = mu;
        sInv[threadIdx.x] = rsqrtf(var + 1e-5f);
    }
    __syncthreads();

    float acc[COUT];
#pragma unroll
    for (int c = 0; c < COUT; c++) acc[c] = 0.f;
#pragma unroll
    for (int j = 0; j < CIN; j++) {
        float v = x[((size_t)(b * CIN + j)) * (SS * KK) + rem];
        v = fmaxf(0.f, (v - sMu[j]) * sInv[j]);
#pragma unroll
        for (int c = 0; c < COUT; c++) acc[c] = fmaf(v, sW[j * COUT + c], acc[c]);
    }
#pragma unroll
    for (int c = 0; c < COUT; c++)
        y[((size_t)(b * COUT + c)) * (SS * KK) + rem] = acc[c];

    int lane = threadIdx.x & 31;
#pragma unroll
    for (int c = 0; c < COUT; c++) {
        float v = acc[c], v2 = v * v;
#pragma unroll
        for (int o = 16; o; o >>= 1) {
            v  += __shfl_down_sync(0xffffffffu, v,  o);
            v2 += __shfl_down_sync(0xffffffffu, v2, o);
        }
        if (lane == 0) { atomicAdd(&sumOut[b * 64 + c], v); atomicAdd(&sqOut[b * 64 + c], v2); }
    }
}

// ---------------- instance-norm + relu + maxpool over K ----------------
template <int C, int SS, bool CHMAJOR>
__global__ void k_maxpool(const float* __restrict__ x,
                          const float* __restrict__ sumIn, const float* __restrict__ sqIn,
                          float* __restrict__ outp)
{
    int t = blockIdx.x * blockDim.x + threadIdx.x;
    int s = t % SS;
    int c = (t / SS) % C;
    int b = t / (SS * C);
    float cnt = (float)(SS * KK);
    float mu = sumIn[b * 64 + c] / cnt;
    float var = sqIn[b * 64 + c] / cnt - mu * mu;
    float inv = rsqrtf(var + 1e-5f);

    const float4* p = reinterpret_cast<const float4*>(
        x + ((size_t)(b * C + c)) * (SS * KK) + (size_t)s * KK);
    float m = -3.4e38f;
#pragma unroll
    for (int qv = 0; qv < KK / 4; qv++) {
        float4 v = p[qv];
        m = fmaxf(m, fmaxf(fmaxf(v.x, v.y), fmaxf(v.z, v.w)));
    }
    float outv = fmaxf(0.f, (m - mu) * inv);
    if (CHMAJOR) outp[(b * C + c) * SS + s] = outv;
    else         outp[(b * SS + s) * C + c] = outv;
}

// ---------------- launch ----------------
extern "C" void kernel_launch(void* const* d_in, const int* in_sizes, int n_in,
                              void* d_out, int out_size)
{
    const float* pc     = (const float*)d_in[0];
    const float* feat   = (const float*)d_in[1];
    const float* sa1_w1 = (const float*)d_in[2];
    const float* sa1_w2 = (const float*)d_in[3];
    const float* sa1_w3 = (const float*)d_in[4];
    const float* sa2_w1 = (const float*)d_in[5];
    const float* sa2_w2 = (const float*)d_in[6];
    const float* sa2_w3 = (const float*)d_in[7];

    float* out = (float*)d_out;
    float* out_pc      = out;
    float* out_pc_l1   = out + 196608;
    float* out_pc_l2   = out + 196608 + 24576;
    float* out_feat_l2 = out + 196608 + 24576 + 12288;
    float* out_fidx1   = out + 196608 + 24576 + 12288 + 262144;
    float* out_fidx2   = out + 196608 + 24576 + 12288 + 262144 + 8192;

    float *xyz0, *feat0, *xyz1, *xyz2, *feat1, *bufA, *bufB, *sum, *sq;
    int *nidx1, *nidx2;
    cudaGetSymbolAddress((void**)&xyz0,  g_xyz0);
    cudaGetSymbolAddress((void**)&feat0, g_feat0);
    cudaGetSymbolAddress((void**)&xyz1,  g_xyz1);
    cudaGetSymbolAddress((void**)&xyz2,  g_xyz2);
    cudaGetSymbolAddress((void**)&feat1, g_feat1);
    cudaGetSymbolAddress((void**)&bufA,  g_bufA);
    cudaGetSymbolAddress((void**)&bufB,  g_bufB);
    cudaGetSymbolAddress((void**)&sum,   g_sum);
    cudaGetSymbolAddress((void**)&sq,    g_sq);
    cudaGetSymbolAddress((void**)&nidx1, g_nidx1);
    cudaGetSymbolAddress((void**)&nidx2, g_nidx2);

    constexpr int CL = 8;                            // cluster size for stage-1 FPS
    constexpr int SMEM1 = 3 * N0 * 4 + 512 * 16;     // full xyz copy + staged rows = 200KB
    constexpr int SMEM2 = 3 * S1V * 4 + 512 * 16;    // 24KB + 8KB = 32KB
    cudaFuncSetAttribute((const void*)k_fps<N0, S1V, 512, CL, 512>,
                         cudaFuncAttributeMaxDynamicSharedMemorySize, SMEM1);
    cudaFuncSetAttribute((const void*)k_fps<S1V, S2V, 512, 1, 512>,
                         cudaFuncAttributeMaxDynamicSharedMemorySize, SMEM2);

    // one-time side streams + events (host objects only; no device allocation)
    static cudaStream_t s1 = nullptr, s2 = nullptr;
    static cudaEvent_t evSeg[4], evPool1, evF2[2], evK2;
    if (!s1) {
        cudaStreamCreateWithFlags(&s1, cudaStreamNonBlocking);
        cudaStreamCreateWithFlags(&s2, cudaStreamNonBlocking);
        for (int i = 0; i < 4; i++) cudaEventCreateWithFlags(&evSeg[i], cudaEventDisableTiming);
        cudaEventCreateWithFlags(&evPool1, cudaEventDisableTiming);
        for (int i = 0; i < 2; i++) cudaEventCreateWithFlags(&evF2[i], cudaEventDisableTiming);
        cudaEventCreateWithFlags(&evK2, cudaEventDisableTiming);
    }

    k_zero<<<6, 256>>>();
    k_transpose<<<768, 256>>>(pc, feat, out_pc);

    // ---- FPS1: 4 cluster-parallel segments on main stream; kNN1/gather1 trail on s1 ----
    for (int seg = 0; seg < 4; seg++) {
        cudaLaunchConfig_t cfg = {};
        cfg.gridDim = dim3(BB * CL, 1, 1);
        cfg.blockDim = dim3(512, 1, 1);
        cfg.dynamicSmemBytes = SMEM1;
        cfg.stream = 0;
        cudaLaunchAttribute attrs[1];
        attrs[0].id = cudaLaunchAttributeClusterDimension;
        attrs[0].val.clusterDim.x = CL;
        attrs[0].val.clusterDim.y = 1;
        attrs[0].val.clusterDim.z = 1;
        cfg.attrs = attrs;
        cfg.numAttrs = 1;
        cudaLaunchKernelEx(&cfg, k_fps<N0, S1V, 512, CL, 512>,
                           (const float*)xyz0, xyz1, out_pc_l1, out_fidx1,
                           seg * 512, (seg + 1) * 512);
        cudaEventRecord(evSeg[seg], 0);
    }
    for (int seg = 0; seg < 4; seg++) {
        cudaStreamWaitEvent(s1, evSeg[seg], 0);
        k_knn<N0, S1V, 2048><<<BB * 512 / 8, 256, 0, s1>>>(xyz1, xyz0, nidx1, seg * 512, 512);
        k_gather_mm<3, 32, S1V, N0><<<(BB * 512 * KK) / 256, 256, 0, s1>>>(
            xyz0, feat0, xyz1, nidx1, sa1_w1, bufA,
            sum + 0 * BB * 64, sq + 0 * BB * 64, seg * 512, 512);
    }
    // stage-1 MLP tail on s1
    k_mm<32, 32, S1V><<<(BB * S1V * KK) / 256, 256, 0, s1>>>(
        bufA, sa1_w2, sum + 0 * BB * 64, sq + 0 * BB * 64, bufB,
        sum + 1 * BB * 64, sq + 1 * BB * 64);
    k_mm<32, 32, S1V><<<(BB * S1V * KK) / 256, 256, 0, s1>>>(
        bufB, sa1_w3, sum + 1 * BB * 64, sq + 1 * BB * 64, bufA,
        sum + 2 * BB * 64, sq + 2 * BB * 64);
    k_maxpool<32, S1V, false><<<(BB * 32 * S1V) / 256, 256, 0, s1>>>(
        bufA, sum + 2 * BB * 64, sq + 2 * BB * 64, feat1);
    cudaEventRecord(evPool1, s1);

    // ---- FPS2 (C=1, T=512) in 2 segments on main; kNN2 chunks trail on s2 ----
    k_fps<S1V, S2V, 512, 1, 512><<<BB, 512, SMEM2>>>(
        xyz1, xyz2, out_pc_l2, out_fidx2, 0, 512);
    cudaEventRecord(evF2[0], 0);
    k_fps<S1V, S2V, 512, 1, 512><<<BB, 512, SMEM2>>>(
        xyz1, xyz2, out_pc_l2, out_fidx2, 512, S2V);
    cudaEventRecord(evF2[1], 0);
    cudaStreamWaitEvent(s2, evF2[0], 0);
    k_knn<S1V, S2V, 2048><<<BB * 512 / 8, 256, 0, s2>>>(xyz2, xyz1, nidx2, 0, 512);
    cudaStreamWaitEvent(s2, evF2[1], 0);
    k_knn<S1V, S2V, 2048><<<BB * 512 / 8, 256, 0, s2>>>(xyz2, xyz1, nidx2, 512, 512);
    cudaEventRecord(evK2, s2);

    // ---- join, then stage-2 MLP on main stream ----
    cudaStreamWaitEvent(0, evPool1, 0);
    cudaStreamWaitEvent(0, evK2, 0);
    k_gather_mm<32, 64, S2V, S1V><<<(BB * S2V * KK) / 256, 256>>>(
        xyz1, feat1, xyz2, nidx2, sa2_w1, bufA,
        sum + 3 * BB * 64, sq + 3 * BB * 64, 0, S2V);
    k_mm<64, 64, S2V><<<(BB * S2V * KK) / 256, 256>>>(
        bufA, sa2_w2, sum + 3 * BB * 64, sq + 3 * BB * 64, bufB,
        sum + 4 * BB * 64, sq + 4 * BB * 64);
    k_mm<64, 64, S2V><<<(BB * S2V * KK) / 256, 256>>>(
        bufB, sa2_w3, sum + 4 * BB * 64, sq + 4 * BB * 64, bufA,
        sum + 5 * BB * 64, sq + 5 * BB * 64);
    k_maxpool<64, S2V, true><<<(BB * 64 * S2V) / 256, 256>>>(
        bufA, sum + 5 * BB * 64, sq + 5 * BB * 64, out_feat_l2);
}

// round 14
// speedup vs baseline: 1.2160x; 1.1799x over previous
#include <cuda_runtime.h>
#include <cstdint>

#define BB  4
#define N0  16384
#define S1V 2048
#define S2V 1024
#define KK  32

// ---------------- device scratch (no allocations allowed) ----------------
__device__ __align__(16) float g_xyz0 [BB * N0  * 3];
__device__ __align__(16) float g_feat0[BB * N0  * 3];
__device__ __align__(16) float g_xyz1 [BB * S1V * 3];
__device__ __align__(16) float g_xyz2 [BB * S2V * 3];
__device__ int   g_nidx1[BB * S1V * KK];
__device__ int   g_nidx2[BB * S2V * KK];
__device__ __align__(16) float g_feat1[BB * S1V * 32];
__device__ __align__(16) float g_bufA [8388608];   // [b][c][s*K+k] channel-major
__device__ __align__(16) float g_bufB [8388608];
__device__ float g_sum[6 * BB * 64];
__device__ float g_sq [6 * BB * 64];
__device__ __align__(16) float g_dist[BB * N0];    // FPS segment-persisted min-dist
__device__ int   g_far[BB];

// ---------------- helpers ----------------
__device__ __forceinline__ unsigned fkey(float f) {
    unsigned u = __float_as_uint(f);
    return u ^ (((unsigned)((int)u >> 31)) | 0x80000000u);
}
__device__ __forceinline__ unsigned long long ullmin2(unsigned long long a, unsigned long long b){return a<b?a:b;}
__device__ __forceinline__ unsigned long long ullmax2(unsigned long long a, unsigned long long b){return a>b?a:b;}

// packed f32x2 ops (Blackwell). Per-lane rounding identical to scalar rn.
__device__ __forceinline__ unsigned long long pk2(float a, float b) {
    unsigned long long r; asm("mov.b64 %0, {%1, %2};" : "=l"(r) : "f"(a), "f"(b)); return r;
}
__device__ __forceinline__ void upk2(unsigned long long v, float& a, float& b) {
    asm("mov.b64 {%0, %1}, %2;" : "=f"(a), "=f"(b) : "l"(v));
}
__device__ __forceinline__ unsigned long long add2(unsigned long long a, unsigned long long b) {
    unsigned long long r; asm("add.rn.f32x2 %0, %1, %2;" : "=l"(r) : "l"(a), "l"(b)); return r;
}
__device__ __forceinline__ unsigned long long mul2(unsigned long long a, unsigned long long b) {
    unsigned long long r; asm("mul.rn.f32x2 %0, %1, %2;" : "=l"(r) : "l"(a), "l"(b)); return r;
}
__device__ __forceinline__ unsigned long long fma2(unsigned long long a, unsigned long long b, unsigned long long c) {
    unsigned long long r; asm("fma.rn.f32x2 %0, %1, %2, %3;" : "=l"(r) : "l"(a), "l"(b), "l"(c)); return r;
}

// warp-uniform reductions (sm_80+)
__device__ __forceinline__ unsigned redux_max(unsigned v) {
    unsigned r; asm volatile("redux.sync.max.u32 %0, %1, 0xffffffff;" : "=r"(r) : "r"(v)); return r;
}
__device__ __forceinline__ unsigned redux_min(unsigned v) {
    unsigned r; asm volatile("redux.sync.min.u32 %0, %1, 0xffffffff;" : "=r"(r) : "r"(v)); return r;
}

// shared-address + cluster comm helpers
__device__ __forceinline__ unsigned smem_u32addr(const void* p) {
    unsigned r;
    asm("{ .reg .u64 t; cvta.to.shared.u64 t, %1; cvt.u32.u64 %0, t; }" : "=r"(r) : "l"(p));
    return r;
}
__device__ __forceinline__ void st_cluster_u64(unsigned laddr, unsigned rank, unsigned long long v) {
    unsigned pa;
    asm volatile("mapa.shared::cluster.u32 %0, %1, %2;" : "=r"(pa) : "r"(laddr), "r"(rank));
    asm volatile("st.shared::cluster.u64 [%0], %1;" :: "r"(pa), "l"(v) : "memory");
}
__device__ __forceinline__ unsigned long long ld_volatile_smem_u64(unsigned laddr) {
    unsigned long long v;
    asm volatile("ld.volatile.shared.u64 %0, [%1];" : "=l"(v) : "r"(laddr) : "memory");
    return v;
}
#define CLUSTER_SYNC() do { \
    asm volatile("barrier.cluster.arrive.aligned;" ::: "memory"); \
    asm volatile("barrier.cluster.wait.aligned;" ::: "memory"); } while (0)

// ---------------- zero stats ----------------
__global__ void k_zero() {
    int t = blockIdx.x * blockDim.x + threadIdx.x;
    if (t < 6 * BB * 64) { g_sum[t] = 0.f; g_sq[t] = 0.f; }
}

// ---------------- transpose [B,3,N] -> [B,N,3] + copy pc to out ----------------
__global__ void k_transpose(const float* __restrict__ pc, const float* __restrict__ feat,
                            float* __restrict__ out_pc) {
    int i = blockIdx.x * blockDim.x + threadIdx.x;
    if (i < BB * 3 * N0) {
        int b = i / (3 * N0);
        int c = (i / N0) % 3;
        int n = i % N0;
        float v = pc[i];
        g_xyz0 [(b * N0 + n) * 3 + c] = v;
        g_feat0[(b * N0 + n) * 3 + c] = feat[i];
        out_pc[i] = v;
    }
}

// ---------------- farthest point sampling (self-flagging packed tuple push) ----------
// LOAD-BEARING for bit-compat with the XLA reference (do not alter):
//   * distance form rn(fma(dz,dz, fma(dy,dy, rn(dx*dx)))) with dx = rn(x + (-cx))
//   * exact GLOBAL max, then 1-ulp tie window with minimum-GLOBAL-index selection
// Cluster protocol (C>1): each CTA packs its tuple into ONE u64:
//   [tag:1 | lmax:31 | argA:16 | argB:16]  (dist>=0 -> lmax bit31==0 frees bit63;
//   local idx < 2048 fits 16 bits; argA always valid, argB sentinel 0xFFFF)
// Lane r stores it to peer r's parity slot via st.shared::cluster.u64 (8B aligned
// stores are single-copy atomic -> the tag IS the release). Consumers poll the
// LOCAL slot until tag == (i>>1)&1 (slot i&1 reused every 2 iters with flipped
// tag -> stale data never matches). Overwrite-before-read impossible by the same
// induction as the mbarrier version. Slots init to tag=1; all segment starts are
// multiples of 4 so the first expected tag is 0.
template <int N, int S, int T, int C, int SEG>
__global__ void __launch_bounds__(T, 1)
k_fps(const float* __restrict__ xyz,
      float* __restrict__ sel_xyz,   // [b][s][3]
      float* __restrict__ out_pc,    // [b][3][S]
      float* __restrict__ out_fidx,  // [b][S] as float
      int i0, int i1)
{
    extern __shared__ float sm[];
    float* sx = sm;
    float* sy = sm + N;
    float* sz = sm + 2 * N;
    float4* sel = (float4*)(sm + 3 * N);       // SEG staged rows (x,y,z,idx)
    constexpr int NW = T / 32;
    constexpr int CS = (C > 1) ? C : 1;
    __shared__ unsigned swmax[NW];
    __shared__ int s_argA[2], s_argB[2];
    __shared__ __align__(8) unsigned long long s_slot[2][CS];

    const int tid = threadIdx.x;
    const int lane = tid & 31;
    const int b = blockIdx.x / C;
    const int rank = blockIdx.x % C;
    constexpr int NL = N / C;        // points per CTA
    constexpr int PL = NL / T;       // points per thread
    constexpr int PAIRS = PL / 2;
    const int base = rank * NL;

    const float* xb = xyz + (size_t)b * N * 3;

    // full xyz copy (centroid lookup only)
    for (int p = tid; p < N; p += T) {
        sx[p] = xb[p * 3 + 0];
        sy[p] = xb[p * 3 + 1];
        sz[p] = xb[p * 3 + 2];
    }
    // register-resident slice
    unsigned long long X[PAIRS], Y[PAIRS], Z[PAIRS];
    float dist[PL];
#pragma unroll
    for (int jj = 0; jj < PAIRS; jj++) {
        int p0 = base + tid + jj * (2 * T);
        int p1 = p0 + T;
        X[jj] = pk2(xb[p0 * 3 + 0], xb[p1 * 3 + 0]);
        Y[jj] = pk2(xb[p0 * 3 + 1], xb[p1 * 3 + 1]);
        Z[jj] = pk2(xb[p0 * 3 + 2], xb[p1 * 3 + 2]);
        if (i0 == 0) { dist[2 * jj] = 1e10f; dist[2 * jj + 1] = 1e10f; }
        else { dist[2 * jj] = g_dist[b * N + p0]; dist[2 * jj + 1] = g_dist[b * N + p1]; }
    }
    int far = (i0 == 0) ? 0 : g_far[b];
    if (tid < 2) { s_argA[tid] = 0x7fffffff; s_argB[tid] = 0x7fffffff; }
    if (tid < 2 * CS) s_slot[tid >> (CS > 1 ? 3 : 0)][tid & (CS - 1)] = ~0ull;  // tag=1
    __syncthreads();
    if constexpr (C > 1) CLUSTER_SYNC();   // all CTAs' slots initialized

    const unsigned a_slot = smem_u32addr(&s_slot[0][0]);

    int ph = 0;
    for (int i = i0; i < i1; i++) {
        const int par = ph;
        float cx = sx[far], cy = sy[far], cz = sz[far];   // broadcast LDS
        if (tid == 0) sel[i - i0] = make_float4(cx, cy, cz, (float)far);
        const unsigned long long ncx2 = pk2(-cx, -cx);
        const unsigned long long ncy2 = pk2(-cy, -cy);
        const unsigned long long ncz2 = pk2(-cz, -cz);
        float mval = 0.f;
#pragma unroll
        for (int jj = 0; jj < PAIRS; jj++) {
            unsigned long long dx = add2(X[jj], ncx2);
            unsigned long long dy = add2(Y[jj], ncy2);
            unsigned long long dz = add2(Z[jj], ncz2);
            unsigned long long t  = mul2(dx, dx);
            t = fma2(dy, dy, t);
            t = fma2(dz, dz, t);
            float da, db; upk2(t, da, db);
            float n0 = fminf(dist[2 * jj],     da);
            float n1 = fminf(dist[2 * jj + 1], db);
            dist[2 * jj]     = n0;
            dist[2 * jj + 1] = n1;
            mval = fmaxf(mval, fmaxf(n0, n1));
        }
        // warp max then block max (dist>=0 -> float bits monotone, max exact)
        unsigned wm = redux_max(__float_as_uint(mval));
        if (lane == 0) swmax[tid >> 5] = wm;
        __syncthreads();                                    // B1
        const unsigned lmax = redux_max(swmax[lane & (NW - 1)]);
        if (lmax - __float_as_uint(mval) <= 1u) {           // candidate threads rescan
#pragma unroll
            for (int j = 0; j < PL; j++) {
                unsigned db = __float_as_uint(dist[j]);
                unsigned diff = lmax - db;
                if (diff <= 1u) {
                    int p = tid + (j >> 1) * (2 * T) + (j & 1) * T;
                    if (diff == 0) atomicMin(&s_argA[par], p);
                    else           atomicMin(&s_argB[par], p);
                }
            }
        }
        __syncthreads();                                    // B2: argA/argB final
        if constexpr (C > 1) {
            const unsigned long long tag = (unsigned long long)((i >> 1) & 1);
            if (tid < C) {   // lane r pushes this CTA's packed tuple to CTA r
                unsigned aA = (unsigned)s_argA[par];               // always valid (<2048)
                unsigned aB = (unsigned)s_argB[par];
                if (aB > 0xFFFEu) aB = 0xFFFFu;                    // sentinel
                unsigned long long pkt = (tag << 63)
                    | ((unsigned long long)lmax << 32)
                    | ((unsigned long long)aA << 16)
                    | (unsigned long long)aB;
                st_cluster_u64(a_slot + 8u * (par * C + rank), (unsigned)tid, pkt);
            }
            if (tid == 32) { s_argA[par ^ 1] = 0x7fffffff; s_argB[par ^ 1] = 0x7fffffff; }
            // poll the LOCAL slot copy; tag match == data valid (8B single-copy atomic)
            const unsigned myaddr = a_slot + 8u * (par * C + (lane & (C - 1)));
            unsigned long long v;
            do { v = ld_volatile_smem_u64(myaddr); } while ((v >> 63) != tag);
            unsigned mb = (unsigned)(v >> 32) & 0x7fffffffu;
            unsigned g = redux_max(mb);                      // exact global max
            unsigned cand = 0x7fffffffu;
            if (lane < C) {
                unsigned aA = (unsigned)(v >> 16) & 0xFFFFu;
                unsigned aB = (unsigned)v & 0xFFFFu;
                unsigned c2 = 0xFFFFu;
                if (mb == g)           c2 = aA < aB ? aA : aB;    // both bins in window
                else if (g - mb == 1u) c2 = aA;                   // only exact bin
                if (c2 != 0xFFFFu) cand = c2 + (unsigned)(lane * NL);
            }
            far = (int)redux_min(cand);                      // min global index
        } else {
            int aA = s_argA[par], aB = s_argB[par];
            far = aA < aB ? aA : aB;                         // min index within window
            if (tid == 32) { s_argA[par ^ 1] = 0x7fffffff; s_argB[par ^ 1] = 0x7fffffff; }
        }
        ph ^= 1;
    }

    if (i1 < S) {   // persist segment state
#pragma unroll
        for (int j = 0; j < PL; j++)
            g_dist[b * N + base + tid + (j >> 1) * (2 * T) + (j & 1) * T] = dist[j];
        if (rank == 0 && tid == 0) g_far[b] = far;
    }
    if (rank == 0) {    // bulk, coalesced output write for positions [i0, i1)
        for (int r = tid; r < i1 - i0; r += T) {
            float4 w = sel[r];
            int i = i0 + r;
            sel_xyz[((size_t)(b * S + i)) * 3 + 0] = w.x;
            sel_xyz[((size_t)(b * S + i)) * 3 + 1] = w.y;
            sel_xyz[((size_t)(b * S + i)) * 3 + 2] = w.z;
            out_pc[b * 3 * S + 0 * S + i] = w.x;
            out_pc[b * 3 * S + 1 * S + i] = w.y;
            out_pc[b * 3 * S + 2 * S + i] = w.z;
            out_fidx[b * S + i] = w.w;
        }
    }
    if constexpr (C > 1) CLUSTER_SYNC();   // exit safety: peers' smem stays live
}

// ---------------- kNN (k=32): warp-cooperative exact bitonic top-32 ----------------
__device__ __forceinline__ unsigned long long bitonic_sort32(unsigned long long v, int lane) {
#pragma unroll
    for (int k = 2; k <= 32; k <<= 1) {
#pragma unroll
        for (int j = k >> 1; j; j >>= 1) {
            unsigned long long o = __shfl_xor_sync(0xffffffffu, v, j);
            bool up    = (lane & k) == 0;
            bool lower = (lane & j) == 0;
            v = (lower == up) ? ullmin2(v, o) : ullmax2(v, o);
        }
    }
    return v;
}
__device__ __forceinline__ unsigned long long bitonic_merge32(unsigned long long v, int lane) {
#pragma unroll
    for (int j = 16; j; j >>= 1) {
        unsigned long long o = __shfl_xor_sync(0xffffffffu, v, j);
        v = ((lane & j) == 0) ? ullmin2(v, o) : ullmax2(v, o);
    }
    return v;
}

template <int N, int S, int CHUNK>
__global__ void k_knn(const float* __restrict__ q, const float* __restrict__ ref,
                      int* __restrict__ nidx, int q0, int nq)
{
    __shared__ float sref[CHUNK * 3];
    const int tid  = threadIdx.x;
    const int lane = tid & 31;
    const int warp = tid >> 5;
    const int per_b = nq / 8;
    const int b = blockIdx.x / per_b;
    const int s = q0 + (blockIdx.x % per_b) * 8 + warp;

    const float qx = q[(b * S + s) * 3 + 0];
    const float qy = q[(b * S + s) * 3 + 1];
    const float qz = q[(b * S + s) * 3 + 2];
    const float qq = fmaf(qz, qz, fmaf(qy, qy, __fmul_rn(qx, qx)));

    unsigned long long topv = ~0ull;
    unsigned long long thr  = ~0ull;

    const float* rb = ref + (size_t)b * N * 3;
    for (int ch = 0; ch < N; ch += CHUNK) {
        for (int i = tid; i < CHUNK * 3; i += 256) sref[i] = rb[ch * 3 + i];
        __syncthreads();
#pragma unroll 2
        for (int c = 0; c < CHUNK / 32; c++) {
            int il = c * 32 + lane;
            float rx = sref[il * 3 + 0];
            float ry = sref[il * 3 + 1];
            float rz = sref[il * 3 + 2];
            float dot = fmaf(qz, rz, fmaf(qy, ry, __fmul_rn(qx, rx)));
            float rr  = fmaf(rz, rz, fmaf(ry, ry, __fmul_rn(rx, rx)));
            float d = __fadd_rn(__fsub_rn(qq, __fmul_rn(2.f, dot)), rr);
            unsigned long long key = ((unsigned long long)fkey(d) << 32) | (unsigned)(ch + il);
            if (__ballot_sync(0xffffffffu, key < thr)) {
                unsigned long long v = bitonic_sort32(key, lane);
                unsigned long long w = __shfl_xor_sync(0xffffffffu, v, 31);
                topv = bitonic_merge32(ullmin2(topv, w), lane);
                thr = __shfl_sync(0xffffffffu, topv, 31);
            }
        }
        __syncthreads();
    }
    nidx[((size_t)(b * S + s)) * KK + lane] = (int)(unsigned)(topv & 0xffffffffu);
}

// ---------------- gather + first 1x1 conv + stats (chunkable over s) ----------------
template <int FDIM, int COUT, int SS, int NREF>
__global__ void k_gather_mm(const float* __restrict__ refxyz,
                            const float* __restrict__ reffeat,
                            const float* __restrict__ newxyz,
                            const int* __restrict__ nidx,
                            const float* __restrict__ W,
                            float* __restrict__ y,
                            float* __restrict__ sum, float* __restrict__ sq,
                            int q0, int nq)
{
    constexpr int CIN = 3 + FDIM;
    __shared__ float sW[CIN * COUT];
    for (int i = threadIdx.x; i < CIN * COUT; i += blockDim.x) sW[i] = W[i];
    __syncthreads();

    int r0 = blockIdx.x * blockDim.x + threadIdx.x;
    int per_b = nq * KK;
    int b = r0 / per_b;
    int rem = q0 * KK + (r0 - b * per_b);
    int s = rem / KK;
    int n = nidx[(size_t)b * (SS * KK) + rem];

    float in[CIN];
#pragma unroll
    for (int c = 0; c < 3; c++)
        in[c] = refxyz[((size_t)(b * NREF + n)) * 3 + c] - newxyz[((size_t)(b * SS + s)) * 3 + c];
#pragma unroll
    for (int j = 0; j < FDIM; j++)
        in[3 + j] = reffeat[((size_t)(b * NREF + n)) * FDIM + j];

    float acc[COUT];
#pragma unroll
    for (int c = 0; c < COUT; c++) acc[c] = 0.f;
#pragma unroll
    for (int j = 0; j < CIN; j++) {
        float v = in[j];
#pragma unroll
        for (int c = 0; c < COUT; c++) acc[c] = fmaf(v, sW[j * COUT + c], acc[c]);
    }
#pragma unroll
    for (int c = 0; c < COUT; c++)
        y[((size_t)(b * COUT + c)) * (SS * KK) + rem] = acc[c];

    int lane = threadIdx.x & 31;
#pragma unroll
    for (int c = 0; c < COUT; c++) {
        float v = acc[c], v2 = v * v;
#pragma unroll
        for (int o = 16; o; o >>= 1) {
            v  += __shfl_down_sync(0xffffffffu, v,  o);
            v2 += __shfl_down_sync(0xffffffffu, v2, o);
        }
        if (lane == 0) { atomicAdd(&sum[b * 64 + c], v); atomicAdd(&sq[b * 64 + c], v2); }
    }
}

// ---------------- instance-norm + relu + 1x1 conv + stats ----------------
template <int CIN, int COUT, int SS>
__global__ void k_mm(const float* __restrict__ x, const float* __restrict__ W,
                     const float* __restrict__ sumIn, const float* __restrict__ sqIn,
                     float* __restrict__ y,
                     float* __restrict__ sumOut, float* __restrict__ sqOut)
{
    __shared__ float sW[CIN * COUT];
    __shared__ float sMu[CIN], sInv[CIN];
    int r = blockIdx.x * blockDim.x + threadIdx.x;
    int b = r / (SS * KK);
    int rem = r - b * (SS * KK);
    for (int i = threadIdx.x; i < CIN * COUT; i += blockDim.x) sW[i] = W[i];
    if (threadIdx.x < CIN) {
        float cnt = (float)(SS * KK);
        float mu = sumIn[b * 64 + threadIdx.x] / cnt;
        float var = sqIn[b * 64 + threadIdx.x] / cnt - mu * mu;
        sMu[threadIdx.x] = mu;
        sInv[threadIdx.x] = rsqrtf(var + 1e-5f);
    }
    __syncthreads();

    float acc[COUT];
#pragma unroll
    for (int c = 0; c < COUT; c++) acc[c] = 0.f;
#pragma unroll
    for (int j = 0; j < CIN; j++) {
        float v = x[((size_t)(b * CIN + j)) * (SS * KK) + rem];
        v = fmaxf(0.f, (v - sMu[j]) * sInv[j]);
#pragma unroll
        for (int c = 0; c < COUT; c++) acc[c] = fmaf(v, sW[j * COUT + c], acc[c]);
    }
#pragma unroll
    for (int c = 0; c < COUT; c++)
        y[((size_t)(b * COUT + c)) * (SS * KK) + rem] = acc[c];

    int lane = threadIdx.x & 31;
#pragma unroll
    for (int c = 0; c < COUT; c++) {
        float v = acc[c], v2 = v * v;
#pragma unroll
        for (int o = 16; o; o >>= 1) {
            v  += __shfl_down_sync(0xffffffffu, v,  o);
            v2 += __shfl_down_sync(0xffffffffu, v2, o);
        }
        if (lane == 0) { atomicAdd(&sumOut[b * 64 + c], v); atomicAdd(&sqOut[b * 64 + c], v2); }
    }
}

// ---------------- instance-norm + relu + maxpool over K ----------------
template <int C, int SS, bool CHMAJOR>
__global__ void k_maxpool(const float* __restrict__ x,
                          const float* __restrict__ sumIn, const float* __restrict__ sqIn,
                          float* __restrict__ outp)
{
    int t = blockIdx.x * blockDim.x + threadIdx.x;
    int s = t % SS;
    int c = (t / SS) % C;
    int b = t / (SS * C);
    float cnt = (float)(SS * KK);
    float mu = sumIn[b * 64 + c] / cnt;
    float var = sqIn[b * 64 + c] / cnt - mu * mu;
    float inv = rsqrtf(var + 1e-5f);

    const float4* p = reinterpret_cast<const float4*>(
        x + ((size_t)(b * C + c)) * (SS * KK) + (size_t)s * KK);
    float m = -3.4e38f;
#pragma unroll
    for (int qv = 0; qv < KK / 4; qv++) {
        float4 v = p[qv];
        m = fmaxf(m, fmaxf(fmaxf(v.x, v.y), fmaxf(v.z, v.w)));
    }
    float outv = fmaxf(0.f, (m - mu) * inv);
    if (CHMAJOR) outp[(b * C + c) * SS + s] = outv;
    else         outp[(b * SS + s) * C + c] = outv;
}

// ---------------- launch ----------------
extern "C" void kernel_launch(void* const* d_in, const int* in_sizes, int n_in,
                              void* d_out, int out_size)
{
    const float* pc     = (const float*)d_in[0];
    const float* feat   = (const float*)d_in[1];
    const float* sa1_w1 = (const float*)d_in[2];
    const float* sa1_w2 = (const float*)d_in[3];
    const float* sa1_w3 = (const float*)d_in[4];
    const float* sa2_w1 = (const float*)d_in[5];
    const float* sa2_w2 = (const float*)d_in[6];
    const float* sa2_w3 = (const float*)d_in[7];

    float* out = (float*)d_out;
    float* out_pc      = out;
    float* out_pc_l1   = out + 196608;
    float* out_pc_l2   = out + 196608 + 24576;
    float* out_feat_l2 = out + 196608 + 24576 + 12288;
    float* out_fidx1   = out + 196608 + 24576 + 12288 + 262144;
    float* out_fidx2   = out + 196608 + 24576 + 12288 + 262144 + 8192;

    float *xyz0, *feat0, *xyz1, *xyz2, *feat1, *bufA, *bufB, *sum, *sq;
    int *nidx1, *nidx2;
    cudaGetSymbolAddress((void**)&xyz0,  g_xyz0);
    cudaGetSymbolAddress((void**)&feat0, g_feat0);
    cudaGetSymbolAddress((void**)&xyz1,  g_xyz1);
    cudaGetSymbolAddress((void**)&xyz2,  g_xyz2);
    cudaGetSymbolAddress((void**)&feat1, g_feat1);
    cudaGetSymbolAddress((void**)&bufA,  g_bufA);
    cudaGetSymbolAddress((void**)&bufB,  g_bufB);
    cudaGetSymbolAddress((void**)&sum,   g_sum);
    cudaGetSymbolAddress((void**)&sq,    g_sq);
    cudaGetSymbolAddress((void**)&nidx1, g_nidx1);
    cudaGetSymbolAddress((void**)&nidx2, g_nidx2);

    constexpr int CL = 8;                            // cluster size for stage-1 FPS
    constexpr int SMEM1 = 3 * N0 * 4 + 512 * 16;     // full xyz copy + staged rows = 200KB
    constexpr int SMEM2 = 3 * S1V * 4 + 1024 * 16;   // 24KB + 16KB = 40KB
    cudaFuncSetAttribute((const void*)k_fps<N0, S1V, 512, CL, 512>,
                         cudaFuncAttributeMaxDynamicSharedMemorySize, SMEM1);
    cudaFuncSetAttribute((const void*)k_fps<S1V, S2V, 512, 1, 1024>,
                         cudaFuncAttributeMaxDynamicSharedMemorySize, SMEM2);

    // one-time side stream + events (host objects only; no device allocation)
    static cudaStream_t s1 = nullptr;
    static cudaEvent_t evSeg[4], evPool1;
    if (!s1) {
        cudaStreamCreateWithFlags(&s1, cudaStreamNonBlocking);
        for (int i = 0; i < 4; i++) cudaEventCreateWithFlags(&evSeg[i], cudaEventDisableTiming);
        cudaEventCreateWithFlags(&evPool1, cudaEventDisableTiming);
    }

    k_zero<<<6, 256>>>();
    k_transpose<<<768, 256>>>(pc, feat, out_pc);

    // ---- FPS1: 4 cluster-parallel segments on main stream; kNN1/gather1 trail on s1 ----
    for (int seg = 0; seg < 4; seg++) {
        cudaLaunchConfig_t cfg = {};
        cfg.gridDim = dim3(BB * CL, 1, 1);
        cfg.blockDim = dim3(512, 1, 1);
        cfg.dynamicSmemBytes = SMEM1;
        cfg.stream = 0;
        cudaLaunchAttribute attrs[1];
        attrs[0].id = cudaLaunchAttributeClusterDimension;
        attrs[0].val.clusterDim.x = CL;
        attrs[0].val.clusterDim.y = 1;
        attrs[0].val.clusterDim.z = 1;
        cfg.attrs = attrs;
        cfg.numAttrs = 1;
        cudaLaunchKernelEx(&cfg, k_fps<N0, S1V, 512, CL, 512>,
                           (const float*)xyz0, xyz1, out_pc_l1, out_fidx1,
                           seg * 512, (seg + 1) * 512);
        cudaEventRecord(evSeg[seg], 0);
    }
    for (int seg = 0; seg < 4; seg++) {
        cudaStreamWaitEvent(s1, evSeg[seg], 0);
        k_knn<N0, S1V, 2048><<<BB * 512 / 8, 256, 0, s1>>>(xyz1, xyz0, nidx1, seg * 512, 512);
        k_gather_mm<3, 32, S1V, N0><<<(BB * 512 * KK) / 256, 256, 0, s1>>>(
            xyz0, feat0, xyz1, nidx1, sa1_w1, bufA,
            sum + 0 * BB * 64, sq + 0 * BB * 64, seg * 512, 512);
    }
    // stage-1 MLP tail on s1
    k_mm<32, 32, S1V><<<(BB * S1V * KK) / 256, 256, 0, s1>>>(
        bufA, sa1_w2, sum + 0 * BB * 64, sq + 0 * BB * 64, bufB,
        sum + 1 * BB * 64, sq + 1 * BB * 64);
    k_mm<32, 32, S1V><<<(BB * S1V * KK) / 256, 256, 0, s1>>>(
        bufB, sa1_w3, sum + 1 * BB * 64, sq + 1 * BB * 64, bufA,
        sum + 2 * BB * 64, sq + 2 * BB * 64);
    k_maxpool<32, S1V, false><<<(BB * 32 * S1V) / 256, 256, 0, s1>>>(
        bufA, sum + 2 * BB * 64, sq + 2 * BB * 64, feat1);
    cudaEventRecord(evPool1, s1);

    // ---- FPS2 (single-CTA-per-batch, C=1) + kNN2 on main stream ----
    k_fps<S1V, S2V, 512, 1, 1024><<<BB, 512, SMEM2>>>(
        xyz1, xyz2, out_pc_l2, out_fidx2, 0, S2V);
    k_knn<S1V, S2V, 2048><<<BB * S2V / 8, 256>>>(xyz2, xyz1, nidx2, 0, S2V);

    // ---- join, then stage-2 MLP on main stream ----
    cudaStreamWaitEvent(0, evPool1, 0);
    k_gather_mm<32, 64, S2V, S1V><<<(BB * S2V * KK) / 256, 256>>>(
        xyz1, feat1, xyz2, nidx2, sa2_w1, bufA,
        sum + 3 * BB * 64, sq + 3 * BB * 64, 0, S2V);
    k_mm<64, 64, S2V><<<(BB * S2V * KK) / 256, 256>>>(
        bufA, sa2_w2, sum + 3 * BB * 64, sq + 3 * BB * 64, bufB,
        sum + 4 * BB * 64, sq + 4 * BB * 64);
    k_mm<64, 64, S2V><<<(BB * S2V * KK) / 256, 256>>>(
        bufB, sa2_w3, sum + 4 * BB * 64, sq + 4 * BB * 64, bufA,
        sum + 5 * BB * 64, sq + 5 * BB * 64);
    k_maxpool<64, S2V, true><<<(BB * 64 * S2V) / 256, 256>>>(
        bufA, sum + 5 * BB * 64, sq + 5 * BB * 64, out_feat_l2);
}

// round 16
// speedup vs baseline: 1.2868x; 1.0582x over previous
#include <cuda_runtime.h>
#include <cstdint>

#define BB  4
#define N0  16384
#define S1V 2048
#define S2V 1024
#define KK  32

// ---------------- device scratch (no allocations allowed) ----------------
__device__ __align__(16) float g_xyz0 [BB * N0  * 3];
__device__ __align__(16) float g_feat0[BB * N0  * 3];
__device__ __align__(16) float g_xyz1 [BB * S1V * 3];
__device__ __align__(16) float g_xyz2 [BB * S2V * 3];
__device__ int   g_nidx1[BB * S1V * KK];
__device__ int   g_nidx2[BB * S2V * KK];
__device__ __align__(16) float g_feat1[BB * S1V * 32];
__device__ __align__(16) float g_bufA [8388608];   // [b][c][s*K+k] channel-major
__device__ __align__(16) float g_bufB [8388608];
__device__ float g_sum[6 * BB * 64];
__device__ float g_sq [6 * BB * 64];
__device__ __align__(16) float g_dist[BB * N0];    // FPS segment-persisted min-dist
__device__ int   g_far[BB];

// ---------------- helpers ----------------
__device__ __forceinline__ unsigned fkey(float f) {
    unsigned u = __float_as_uint(f);
    return u ^ (((unsigned)((int)u >> 31)) | 0x80000000u);
}
__device__ __forceinline__ unsigned long long ullmin2(unsigned long long a, unsigned long long b){return a<b?a:b;}
__device__ __forceinline__ unsigned long long ullmax2(unsigned long long a, unsigned long long b){return a>b?a:b;}

// packed f32x2 ops (Blackwell). Per-lane rounding identical to scalar rn.
__device__ __forceinline__ unsigned long long pk2(float a, float b) {
    unsigned long long r; asm("mov.b64 %0, {%1, %2};" : "=l"(r) : "f"(a), "f"(b)); return r;
}
__device__ __forceinline__ void upk2(unsigned long long v, float& a, float& b) {
    asm("mov.b64 {%0, %1}, %2;" : "=f"(a), "=f"(b) : "l"(v));
}
__device__ __forceinline__ unsigned long long add2(unsigned long long a, unsigned long long b) {
    unsigned long long r; asm("add.rn.f32x2 %0, %1, %2;" : "=l"(r) : "l"(a), "l"(b)); return r;
}
__device__ __forceinline__ unsigned long long mul2(unsigned long long a, unsigned long long b) {
    unsigned long long r; asm("mul.rn.f32x2 %0, %1, %2;" : "=l"(r) : "l"(a), "l"(b)); return r;
}
__device__ __forceinline__ unsigned long long fma2(unsigned long long a, unsigned long long b, unsigned long long c) {
    unsigned long long r; asm("fma.rn.f32x2 %0, %1, %2, %3;" : "=l"(r) : "l"(a), "l"(b), "l"(c)); return r;
}

// warp-uniform reductions (sm_80+)
__device__ __forceinline__ unsigned redux_max(unsigned v) {
    unsigned r; asm volatile("redux.sync.max.u32 %0, %1, 0xffffffff;" : "=r"(r) : "r"(v)); return r;
}
__device__ __forceinline__ unsigned redux_min(unsigned v) {
    unsigned r; asm volatile("redux.sync.min.u32 %0, %1, 0xffffffff;" : "=r"(r) : "r"(v)); return r;
}

// shared-address + cluster comm helpers
__device__ __forceinline__ unsigned smem_u32addr(const void* p) {
    unsigned r;
    asm("{ .reg .u64 t; cvta.to.shared.u64 t, %1; cvt.u32.u64 %0, t; }" : "=r"(r) : "l"(p));
    return r;
}
__device__ __forceinline__ void st_cluster_u64(unsigned laddr, unsigned rank, unsigned long long v) {
    unsigned pa;
    asm volatile("mapa.shared::cluster.u32 %0, %1, %2;" : "=r"(pa) : "r"(laddr), "r"(rank));
    asm volatile("st.shared::cluster.u64 [%0], %1;" :: "r"(pa), "l"(v) : "memory");
}
__device__ __forceinline__ unsigned long long ld_volatile_smem_u64(unsigned laddr) {
    unsigned long long v;
    asm volatile("ld.volatile.shared.u64 %0, [%1];" : "=l"(v) : "r"(laddr) : "memory");
    return v;
}
#define CLUSTER_SYNC() do { \
    asm volatile("barrier.cluster.arrive.aligned;" ::: "memory"); \
    asm volatile("barrier.cluster.wait.aligned;" ::: "memory"); } while (0)

// ---------------- zero stats ----------------
__global__ void k_zero() {
    int t = blockIdx.x * blockDim.x + threadIdx.x;
    if (t < 6 * BB * 64) { g_sum[t] = 0.f; g_sq[t] = 0.f; }
}

// ---------------- transpose [B,3,N] -> [B,N,3] + copy pc to out ----------------
__global__ void k_transpose(const float* __restrict__ pc, const float* __restrict__ feat,
                            float* __restrict__ out_pc) {
    int i = blockIdx.x * blockDim.x + threadIdx.x;
    if (i < BB * 3 * N0) {
        int b = i / (3 * N0);
        int c = (i / N0) % 3;
        int n = i % N0;
        float v = pc[i];
        g_xyz0 [(b * N0 + n) * 3 + c] = v;
        g_feat0[(b * N0 + n) * 3 + c] = feat[i];
        out_pc[i] = v;
    }
}

// ---------------- stage-2 "FPS": provably the identity permutation --------------------
// FPS over xyz1 starting at index 0 selects positions 0..S2V-1 in order:
// by induction both runs share picks; selected positions have dist == 0 exactly
// (q==c -> d computes to +0), position i attains the global max (same fminf-
// accumulated f32 dist values), so first-max argmax returns i. Hence
// xyz2 = xyz1[:,0:1024,:] and fidx2 = iota. No FPS compute needed.
__global__ void k_l2out(const float* __restrict__ xyz1,
                        float* __restrict__ xyz2,      // [b][1024][3]
                        float* __restrict__ out_pc2,   // [b][3][1024]
                        float* __restrict__ out_fidx2) // [b][1024]
{
    int t = blockIdx.x * blockDim.x + threadIdx.x;     // over BB*S2V
    int b = t / S2V;
    int i = t % S2V;
    float x = xyz1[((size_t)(b * S1V + i)) * 3 + 0];
    float y = xyz1[((size_t)(b * S1V + i)) * 3 + 1];
    float z = xyz1[((size_t)(b * S1V + i)) * 3 + 2];
    xyz2[((size_t)(b * S2V + i)) * 3 + 0] = x;
    xyz2[((size_t)(b * S2V + i)) * 3 + 1] = y;
    xyz2[((size_t)(b * S2V + i)) * 3 + 2] = z;
    out_pc2[b * 3 * S2V + 0 * S2V + i] = x;
    out_pc2[b * 3 * S2V + 1 * S2V + i] = y;
    out_pc2[b * 3 * S2V + 2 * S2V + i] = z;
    out_fidx2[b * S2V + i] = (float)i;
}

// ---------------- farthest point sampling (self-flagging packed tuple push) ----------
// LOAD-BEARING for bit-compat with the XLA reference (do not alter):
//   * distance form rn(fma(dz,dz, fma(dy,dy, rn(dx*dx)))) with dx = rn(x + (-cx))
//   * exact GLOBAL max, then 1-ulp tie window with minimum-GLOBAL-index selection
// Cluster protocol (C>1): each CTA packs its tuple into ONE u64:
//   [tag:1 | lmax:31 | argA:16 | argB:16]  (dist>=0 -> lmax bit31==0 frees bit63;
//   local idx < 2048 fits 16 bits; argA always valid, argB sentinel 0xFFFF)
// Lane r stores it to peer r's parity slot via st.shared::cluster.u64 (8B aligned
// stores are single-copy atomic -> the tag IS the release). Consumers poll the
// LOCAL slot until tag == (i>>1)&1 (slot i&1 reused every 2 iters with flipped
// tag -> stale data never matches). Overwrite-before-read impossible by the same
// induction as the mbarrier version. Slots init to tag=1; all segment starts are
// multiples of 4 so the first expected tag is 0.
template <int N, int S, int T, int C, int SEG>
__global__ void __launch_bounds__(T, 1)
k_fps(const float* __restrict__ xyz,
      float* __restrict__ sel_xyz,   // [b][s][3]
      float* __restrict__ out_pc,    // [b][3][S]
      float* __restrict__ out_fidx,  // [b][S] as float
      int i0, int i1)
{
    extern __shared__ float sm[];
    float* sx = sm;
    float* sy = sm + N;
    float* sz = sm + 2 * N;
    float4* sel = (float4*)(sm + 3 * N);       // SEG staged rows (x,y,z,idx)
    constexpr int NW = T / 32;
    constexpr int CS = (C > 1) ? C : 1;
    __shared__ unsigned swmax[NW];
    __shared__ int s_argA[2], s_argB[2];
    __shared__ __align__(8) unsigned long long s_slot[2][CS];

    const int tid = threadIdx.x;
    const int lane = tid & 31;
    const int b = blockIdx.x / C;
    const int rank = blockIdx.x % C;
    constexpr int NL = N / C;        // points per CTA
    constexpr int PL = NL / T;       // points per thread
    constexpr int PAIRS = PL / 2;
    const int base = rank * NL;

    const float* xb = xyz + (size_t)b * N * 3;

    // full xyz copy (centroid lookup only)
    for (int p = tid; p < N; p += T) {
        sx[p] = xb[p * 3 + 0];
        sy[p] = xb[p * 3 + 1];
        sz[p] = xb[p * 3 + 2];
    }
    // register-resident slice
    unsigned long long X[PAIRS], Y[PAIRS], Z[PAIRS];
    float dist[PL];
#pragma unroll
    for (int jj = 0; jj < PAIRS; jj++) {
        int p0 = base + tid + jj * (2 * T);
        int p1 = p0 + T;
        X[jj] = pk2(xb[p0 * 3 + 0], xb[p1 * 3 + 0]);
        Y[jj] = pk2(xb[p0 * 3 + 1], xb[p1 * 3 + 1]);
        Z[jj] = pk2(xb[p0 * 3 + 2], xb[p1 * 3 + 2]);
        if (i0 == 0) { dist[2 * jj] = 1e10f; dist[2 * jj + 1] = 1e10f; }
        else { dist[2 * jj] = g_dist[b * N + p0]; dist[2 * jj + 1] = g_dist[b * N + p1]; }
    }
    int far = (i0 == 0) ? 0 : g_far[b];
    if (tid < 2) { s_argA[tid] = 0x7fffffff; s_argB[tid] = 0x7fffffff; }
    if (tid < 2 * CS) s_slot[tid >> (CS > 1 ? 3 : 0)][tid & (CS - 1)] = ~0ull;  // tag=1
    __syncthreads();
    if constexpr (C > 1) CLUSTER_SYNC();   // all CTAs' slots initialized

    const unsigned a_slot = smem_u32addr(&s_slot[0][0]);

    int ph = 0;
    for (int i = i0; i < i1; i++) {
        const int par = ph;
        float cx = sx[far], cy = sy[far], cz = sz[far];   // broadcast LDS
        if (tid == 0) sel[i - i0] = make_float4(cx, cy, cz, (float)far);
        const unsigned long long ncx2 = pk2(-cx, -cx);
        const unsigned long long ncy2 = pk2(-cy, -cy);
        const unsigned long long ncz2 = pk2(-cz, -cz);
        float mval = 0.f;
#pragma unroll
        for (int jj = 0; jj < PAIRS; jj++) {
            unsigned long long dx = add2(X[jj], ncx2);
            unsigned long long dy = add2(Y[jj], ncy2);
            unsigned long long dz = add2(Z[jj], ncz2);
            unsigned long long t  = mul2(dx, dx);
            t = fma2(dy, dy, t);
            t = fma2(dz, dz, t);
            float da, db; upk2(t, da, db);
            float n0 = fminf(dist[2 * jj],     da);
            float n1 = fminf(dist[2 * jj + 1], db);
            dist[2 * jj]     = n0;
            dist[2 * jj + 1] = n1;
            mval = fmaxf(mval, fmaxf(n0, n1));
        }
        // warp max then block max (dist>=0 -> float bits monotone, max exact)
        unsigned wm = redux_max(__float_as_uint(mval));
        if (lane == 0) swmax[tid >> 5] = wm;
        __syncthreads();                                    // B1
        const unsigned lmax = redux_max(swmax[lane & (NW - 1)]);
        if (lmax - __float_as_uint(mval) <= 1u) {           // candidate threads rescan
#pragma unroll
            for (int j = 0; j < PL; j++) {
                unsigned db = __float_as_uint(dist[j]);
                unsigned diff = lmax - db;
                if (diff <= 1u) {
                    int p = tid + (j >> 1) * (2 * T) + (j & 1) * T;
                    if (diff == 0) atomicMin(&s_argA[par], p);
                    else           atomicMin(&s_argB[par], p);
                }
            }
        }
        __syncthreads();                                    // B2: argA/argB final
        if constexpr (C > 1) {
            const unsigned long long tag = (unsigned long long)((i >> 1) & 1);
            if (tid < C) {   // lane r pushes this CTA's packed tuple to CTA r
                unsigned aA = (unsigned)s_argA[par];               // always valid (<2048)
                unsigned aB = (unsigned)s_argB[par];
                if (aB > 0xFFFEu) aB = 0xFFFFu;                    // sentinel
                unsigned long long pkt = (tag << 63)
                    | ((unsigned long long)lmax << 32)
                    | ((unsigned long long)aA << 16)
                    | (unsigned long long)aB;
                st_cluster_u64(a_slot + 8u * (par * C + rank), (unsigned)tid, pkt);
            }
            if (tid == 32) { s_argA[par ^ 1] = 0x7fffffff; s_argB[par ^ 1] = 0x7fffffff; }
            // poll the LOCAL slot copy; tag match == data valid (8B single-copy atomic)
            const unsigned myaddr = a_slot + 8u * (par * C + (lane & (C - 1)));
            unsigned long long v;
            do { v = ld_volatile_smem_u64(myaddr); } while ((v >> 63) != tag);
            unsigned mb = (unsigned)(v >> 32) & 0x7fffffffu;
            unsigned g = redux_max(mb);                      // exact global max
            unsigned cand = 0x7fffffffu;
            if (lane < C) {
                unsigned aA = (unsigned)(v >> 16) & 0xFFFFu;
                unsigned aB = (unsigned)v & 0xFFFFu;
                unsigned c2 = 0xFFFFu;
                if (mb == g)           c2 = aA < aB ? aA : aB;    // both bins in window
                else if (g - mb == 1u) c2 = aA;                   // only exact bin
                if (c2 != 0xFFFFu) cand = c2 + (unsigned)(lane * NL);
            }
            far = (int)redux_min(cand);                      // min global index
        } else {
            int aA = s_argA[par], aB = s_argB[par];
            far = aA < aB ? aA : aB;                         // min index within window
            if (tid == 32) { s_argA[par ^ 1] = 0x7fffffff; s_argB[par ^ 1] = 0x7fffffff; }
        }
        ph ^= 1;
    }

    if (i1 < S) {   // persist segment state
#pragma unroll
        for (int j = 0; j < PL; j++)
            g_dist[b * N + base + tid + (j >> 1) * (2 * T) + (j & 1) * T] = dist[j];
        if (rank == 0 && tid == 0) g_far[b] = far;
    }
    if (rank == 0) {    // bulk, coalesced output write for positions [i0, i1)
        for (int r = tid; r < i1 - i0; r += T) {
            float4 w = sel[r];
            int i = i0 + r;
            sel_xyz[((size_t)(b * S + i)) * 3 + 0] = w.x;
            sel_xyz[((size_t)(b * S + i)) * 3 + 1] = w.y;
            sel_xyz[((size_t)(b * S + i)) * 3 + 2] = w.z;
            out_pc[b * 3 * S + 0 * S + i] = w.x;
            out_pc[b * 3 * S + 1 * S + i] = w.y;
            out_pc[b * 3 * S + 2 * S + i] = w.z;
            out_fidx[b * S + i] = w.w;
        }
    }
    if constexpr (C > 1) CLUSTER_SYNC();   // exit safety: peers' smem stays live
}

// ---------------- kNN (k=32): warp-cooperative exact bitonic top-32 ----------------
__device__ __forceinline__ unsigned long long bitonic_sort32(unsigned long long v, int lane) {
#pragma unroll
    for (int k = 2; k <= 32; k <<= 1) {
#pragma unroll
        for (int j = k >> 1; j; j >>= 1) {
            unsigned long long o = __shfl_xor_sync(0xffffffffu, v, j);
            bool up    = (lane & k) == 0;
            bool lower = (lane & j) == 0;
            v = (lower == up) ? ullmin2(v, o) : ullmax2(v, o);
        }
    }
    return v;
}
__device__ __forceinline__ unsigned long long bitonic_merge32(unsigned long long v, int lane) {
#pragma unroll
    for (int j = 16; j; j >>= 1) {
        unsigned long long o = __shfl_xor_sync(0xffffffffu, v, j);
        v = ((lane & j) == 0) ? ullmin2(v, o) : ullmax2(v, o);
    }
    return v;
}

template <int N, int S, int CHUNK>
__global__ void k_knn(const float* __restrict__ q, const float* __restrict__ ref,
                      int* __restrict__ nidx, int q0, int nq)
{
    __shared__ float sref[CHUNK * 3];
    const int tid  = threadIdx.x;
    const int lane = tid & 31;
    const int warp = tid >> 5;
    const int per_b = nq / 8;
    const int b = blockIdx.x / per_b;
    const int s = q0 + (blockIdx.x % per_b) * 8 + warp;

    const float qx = q[(b * S + s) * 3 + 0];
    const float qy = q[(b * S + s) * 3 + 1];
    const float qz = q[(b * S + s) * 3 + 2];
    const float qq = fmaf(qz, qz, fmaf(qy, qy, __fmul_rn(qx, qx)));

    unsigned long long topv = ~0ull;
    unsigned long long thr  = ~0ull;

    const float* rb = ref + (size_t)b * N * 3;
    for (int ch = 0; ch < N; ch += CHUNK) {
        for (int i = tid; i < CHUNK * 3; i += 256) sref[i] = rb[ch * 3 + i];
        __syncthreads();
#pragma unroll 2
        for (int c = 0; c < CHUNK / 32; c++) {
            int il = c * 32 + lane;
            float rx = sref[il * 3 + 0];
            float ry = sref[il * 3 + 1];
            float rz = sref[il * 3 + 2];
            float dot = fmaf(qz, rz, fmaf(qy, ry, __fmul_rn(qx, rx)));
            float rr  = fmaf(rz, rz, fmaf(ry, ry, __fmul_rn(rx, rx)));
            float d = __fadd_rn(__fsub_rn(qq, __fmul_rn(2.f, dot)), rr);
            unsigned long long key = ((unsigned long long)fkey(d) << 32) | (unsigned)(ch + il);
            if (__ballot_sync(0xffffffffu, key < thr)) {
                unsigned long long v = bitonic_sort32(key, lane);
                unsigned long long w = __shfl_xor_sync(0xffffffffu, v, 31);
                topv = bitonic_merge32(ullmin2(topv, w), lane);
                thr = __shfl_sync(0xffffffffu, topv, 31);
            }
        }
        __syncthreads();
    }
    nidx[((size_t)(b * S + s)) * KK + lane] = (int)(unsigned)(topv & 0xffffffffu);
}

// ---------------- gather + first 1x1 conv + stats (chunkable over s) ----------------
template <int FDIM, int COUT, int SS, int NREF>
__global__ void k_gather_mm(const float* __restrict__ refxyz,
                            const float* __restrict__ reffeat,
                            const float* __restrict__ newxyz,
                            const int* __restrict__ nidx,
                            const float* __restrict__ W,
                            float* __restrict__ y,
                            float* __restrict__ sum, float* __restrict__ sq,
                            int q0, int nq)
{
    constexpr int CIN = 3 + FDIM;
    __shared__ float sW[CIN * COUT];
    for (int i = threadIdx.x; i < CIN * COUT; i += blockDim.x) sW[i] = W[i];
    __syncthreads();

    int r0 = blockIdx.x * blockDim.x + threadIdx.x;
    int per_b = nq * KK;
    int b = r0 / per_b;
    int rem = q0 * KK + (r0 - b * per_b);
    int s = rem / KK;
    int n = nidx[(size_t)b * (SS * KK) + rem];

    float in[CIN];
#pragma unroll
    for (int c = 0; c < 3; c++)
        in[c] = refxyz[((size_t)(b * NREF + n)) * 3 + c] - newxyz[((size_t)(b * SS + s)) * 3 + c];
#pragma unroll
    for (int j = 0; j < FDIM; j++)
        in[3 + j] = reffeat[((size_t)(b * NREF + n)) * FDIM + j];

    float acc[COUT];
#pragma unroll
    for (int c = 0; c < COUT; c++) acc[c] = 0.f;
#pragma unroll
    for (int j = 0; j < CIN; j++) {
        float v = in[j];
#pragma unroll
        for (int c = 0; c < COUT; c++) acc[c] = fmaf(v, sW[j * COUT + c], acc[c]);
    }
#pragma unroll
    for (int c = 0; c < COUT; c++)
        y[((size_t)(b * COUT + c)) * (SS * KK) + rem] = acc[c];

    int lane = threadIdx.x & 31;
#pragma unroll
    for (int c = 0; c < COUT; c++) {
        float v = acc[c], v2 = v * v;
#pragma unroll
        for (int o = 16; o; o >>= 1) {
            v  += __shfl_down_sync(0xffffffffu, v,  o);
            v2 += __shfl_down_sync(0xffffffffu, v2, o);
        }
        if (lane == 0) { atomicAdd(&sum[b * 64 + c], v); atomicAdd(&sq[b * 64 + c], v2); }
    }
}

// ---------------- instance-norm + relu + 1x1 conv + stats ----------------
template <int CIN, int COUT, int SS>
__global__ void k_mm(const float* __restrict__ x, const float* __restrict__ W,
                     const float* __restrict__ sumIn, const float* __restrict__ sqIn,
                     float* __restrict__ y,
                     float* __restrict__ sumOut, float* __restrict__ sqOut)
{
    __shared__ float sW[CIN * COUT];
    __shared__ float sMu[CIN], sInv[CIN];
    int r = blockIdx.x * blockDim.x + threadIdx.x;
    int b = r / (SS * KK);
    int rem = r - b * (SS * KK);
    for (int i = threadIdx.x; i < CIN * COUT; i += blockDim.x) sW[i] = W[i];
    if (threadIdx.x < CIN) {
        float cnt = (float)(SS * KK);
        float mu = sumIn[b * 64 + threadIdx.x] / cnt;
        float var = sqIn[b * 64 + threadIdx.x] / cnt - mu * mu;
        sMu[threadIdx.x] = mu;
        sInv[threadIdx.x] = rsqrtf(var + 1e-5f);
    }
    __syncthreads();

    float acc[COUT];
#pragma unroll
    for (int c = 0; c < COUT; c++) acc[c] = 0.f;
#pragma unroll
    for (int j = 0; j < CIN; j++) {
        float v = x[((size_t)(b * CIN + j)) * (SS * KK) + rem];
        v = fmaxf(0.f, (v - sMu[j]) * sInv[j]);
#pragma unroll
        for (int c = 0; c < COUT; c++) acc[c] = fmaf(v, sW[j * COUT + c], acc[c]);
    }
#pragma unroll
    for (int c = 0; c < COUT; c++)
        y[((size_t)(b * COUT + c)) * (SS * KK) + rem] = acc[c];

    int lane = threadIdx.x & 31;
#pragma unroll
    for (int c = 0; c < COUT; c++) {
        float v = acc[c], v2 = v * v;
#pragma unroll
        for (int o = 16; o; o >>= 1) {
            v  += __shfl_down_sync(0xffffffffu, v,  o);
            v2 += __shfl_down_sync(0xffffffffu, v2, o);
        }
        if (lane == 0) { atomicAdd(&sumOut[b * 64 + c], v); atomicAdd(&sqOut[b * 64 + c], v2); }
    }
}

// ---------------- instance-norm + relu + maxpool over K ----------------
template <int C, int SS, bool CHMAJOR>
__global__ void k_maxpool(const float* __restrict__ x,
                          const float* __restrict__ sumIn, const float* __restrict__ sqIn,
                          float* __restrict__ outp)
{
    int t = blockIdx.x * blockDim.x + threadIdx.x;
    int s = t % SS;
    int c = (t / SS) % C;
    int b = t / (SS * C);
    float cnt = (float)(SS * KK);
    float mu = sumIn[b * 64 + c] / cnt;
    float var = sqIn[b * 64 + c] / cnt - mu * mu;
    float inv = rsqrtf(var + 1e-5f);

    const float4* p = reinterpret_cast<const float4*>(
        x + ((size_t)(b * C + c)) * (SS * KK) + (size_t)s * KK);
    float m = -3.4e38f;
#pragma unroll
    for (int qv = 0; qv < KK / 4; qv++) {
        float4 v = p[qv];
        m = fmaxf(m, fmaxf(fmaxf(v.x, v.y), fmaxf(v.z, v.w)));
    }
    float outv = fmaxf(0.f, (m - mu) * inv);
    if (CHMAJOR) outp[(b * C + c) * SS + s] = outv;
    else         outp[(b * SS + s) * C + c] = outv;
}

// ---------------- launch ----------------
extern "C" void kernel_launch(void* const* d_in, const int* in_sizes, int n_in,
                              void* d_out, int out_size)
{
    const float* pc     = (const float*)d_in[0];
    const float* feat   = (const float*)d_in[1];
    const float* sa1_w1 = (const float*)d_in[2];
    const float* sa1_w2 = (const float*)d_in[3];
    const float* sa1_w3 = (const float*)d_in[4];
    const float* sa2_w1 = (const float*)d_in[5];
    const float* sa2_w2 = (const float*)d_in[6];
    const float* sa2_w3 = (const float*)d_in[7];

    float* out = (float*)d_out;
    float* out_pc      = out;
    float* out_pc_l1   = out + 196608;
    float* out_pc_l2   = out + 196608 + 24576;
    float* out_feat_l2 = out + 196608 + 24576 + 12288;
    float* out_fidx1   = out + 196608 + 24576 + 12288 + 262144;
    float* out_fidx2   = out + 196608 + 24576 + 12288 + 262144 + 8192;

    float *xyz0, *feat0, *xyz1, *xyz2, *feat1, *bufA, *bufB, *sum, *sq;
    int *nidx1, *nidx2;
    cudaGetSymbolAddress((void**)&xyz0,  g_xyz0);
    cudaGetSymbolAddress((void**)&feat0, g_feat0);
    cudaGetSymbolAddress((void**)&xyz1,  g_xyz1);
    cudaGetSymbolAddress((void**)&xyz2,  g_xyz2);
    cudaGetSymbolAddress((void**)&feat1, g_feat1);
    cudaGetSymbolAddress((void**)&bufA,  g_bufA);
    cudaGetSymbolAddress((void**)&bufB,  g_bufB);
    cudaGetSymbolAddress((void**)&sum,   g_sum);
    cudaGetSymbolAddress((void**)&sq,    g_sq);
    cudaGetSymbolAddress((void**)&nidx1, g_nidx1);
    cudaGetSymbolAddress((void**)&nidx2, g_nidx2);

    constexpr int CL = 8;                            // cluster size for stage-1 FPS
    constexpr int SMEM1 = 3 * N0 * 4 + 512 * 16;     // full xyz copy + staged rows = 200KB
    cudaFuncSetAttribute((const void*)k_fps<N0, S1V, 512, CL, 512>,
                         cudaFuncAttributeMaxDynamicSharedMemorySize, SMEM1);

    // one-time side stream + events (host objects only; no device allocation)
    static cudaStream_t s1 = nullptr;
    static cudaEvent_t evSeg[4], evPool1;
    if (!s1) {
        cudaStreamCreateWithFlags(&s1, cudaStreamNonBlocking);
        for (int i = 0; i < 4; i++) cudaEventCreateWithFlags(&evSeg[i], cudaEventDisableTiming);
        cudaEventCreateWithFlags(&evPool1, cudaEventDisableTiming);
    }

    k_zero<<<6, 256>>>();
    k_transpose<<<768, 256>>>(pc, feat, out_pc);

    // ---- FPS1: 4 cluster-parallel segments on main stream; kNN1/gather1 trail on s1 ----
    for (int seg = 0; seg < 4; seg++) {
        cudaLaunchConfig_t cfg = {};
        cfg.gridDim = dim3(BB * CL, 1, 1);
        cfg.blockDim = dim3(512, 1, 1);
        cfg.dynamicSmemBytes = SMEM1;
        cfg.stream = 0;
        cudaLaunchAttribute attrs[1];
        attrs[0].id = cudaLaunchAttributeClusterDimension;
        attrs[0].val.clusterDim.x = CL;
        attrs[0].val.clusterDim.y = 1;
        attrs[0].val.clusterDim.z = 1;
        cfg.attrs = attrs;
        cfg.numAttrs = 1;
        cudaLaunchKernelEx(&cfg, k_fps<N0, S1V, 512, CL, 512>,
                           (const float*)xyz0, xyz1, out_pc_l1, out_fidx1,
                           seg * 512, (seg + 1) * 512);
        cudaEventRecord(evSeg[seg], 0);
    }
    for (int seg = 0; seg < 4; seg++) {
        cudaStreamWaitEvent(s1, evSeg[seg], 0);
        k_knn<N0, S1V, 2048><<<BB * 512 / 8, 256, 0, s1>>>(xyz1, xyz0, nidx1, seg * 512, 512);
        k_gather_mm<3, 32, S1V, N0><<<(BB * 512 * KK) / 256, 256, 0, s1>>>(
            xyz0, feat0, xyz1, nidx1, sa1_w1, bufA,
            sum + 0 * BB * 64, sq + 0 * BB * 64, seg * 512, 512);
    }
    // stage-1 MLP tail on s1
    k_mm<32, 32, S1V><<<(BB * S1V * KK) / 256, 256, 0, s1>>>(
        bufA, sa1_w2, sum + 0 * BB * 64, sq + 0 * BB * 64, bufB,
        sum + 1 * BB * 64, sq + 1 * BB * 64);
    k_mm<32, 32, S1V><<<(BB * S1V * KK) / 256, 256, 0, s1>>>(
        bufB, sa1_w3, sum + 1 * BB * 64, sq + 1 * BB * 64, bufA,
        sum + 2 * BB * 64, sq + 2 * BB * 64);
    k_maxpool<32, S1V, false><<<(BB * 32 * S1V) / 256, 256, 0, s1>>>(
        bufA, sum + 2 * BB * 64, sq + 2 * BB * 64, feat1);
    cudaEventRecord(evPool1, s1);

    // ---- stage-2 sampling is the identity: copy prefix + iota, then kNN2 ----
    k_l2out<<<(BB * S2V) / 256, 256>>>(xyz1, xyz2, out_pc_l2, out_fidx2);
    k_knn<S1V, S2V, 2048><<<BB * S2V / 8, 256>>>(xyz2, xyz1, nidx2, 0, S2V);

    // ---- join, then stage-2 MLP on main stream ----
    cudaStreamWaitEvent(0, evPool1, 0);
    k_gather_mm<32, 64, S2V, S1V><<<(BB * S2V * KK) / 256, 256>>>(
        xyz1, feat1, xyz2, nidx2, sa2_w1, bufA,
        sum + 3 * BB * 64, sq + 3 * BB * 64, 0, S2V);
    k_mm<64, 64, S2V><<<(BB * S2V * KK) / 256, 256>>>(
        bufA, sa2_w2, sum + 3 * BB * 64, sq + 3 * BB * 64, bufB,
        sum + 4 * BB * 64, sq + 4 * BB * 64);
    k_mm<64, 64, S2V><<<(BB * S2V * KK) / 256, 256>>>(
        bufB, sa2_w3, sum + 4 * BB * 64, sq + 4 * BB * 64, bufA,
        sum + 5 * BB * 64, sq + 5 * BB * 64);
    k_maxpool<64, S2V, true><<<(BB * 64 * S2V) / 256, 256>>>(
        bufA, sum + 5 * BB * 64, sq + 5 * BB * 64, out_feat_l2);
}

// round 17
// speedup vs baseline: 1.3285x; 1.0324x over previous
#include <cuda_runtime.h>
#include <cstdint>

#define BB  4
#define N0  16384
#define S1V 2048
#define S2V 1024
#define KK  32

// ---------------- device scratch (no allocations allowed) ----------------
__device__ __align__(16) float g_xyz0 [BB * N0  * 3];
__device__ __align__(16) float g_feat0[BB * N0  * 3];
__device__ __align__(16) float g_xyz1 [BB * S1V * 3];
__device__ __align__(16) float g_xyz2 [BB * S2V * 3];
__device__ int   g_nidx1[BB * S1V * KK];
__device__ int   g_nidx2[BB * S2V * KK];
__device__ __align__(16) float g_feat1[BB * S1V * 32];
__device__ __align__(16) float g_bufA [8388608];   // [b][c][s*K+k] channel-major
__device__ __align__(16) float g_bufB [8388608];
__device__ float g_sum[6 * BB * 64];
__device__ float g_sq [6 * BB * 64];
__device__ __align__(16) float g_dist[BB * N0];    // FPS segment-persisted min-dist
__device__ int   g_far[BB];

// ---------------- helpers ----------------
__device__ __forceinline__ unsigned fkey(float f) {
    unsigned u = __float_as_uint(f);
    return u ^ (((unsigned)((int)u >> 31)) | 0x80000000u);
}
__device__ __forceinline__ unsigned long long ullmin2(unsigned long long a, unsigned long long b){return a<b?a:b;}
__device__ __forceinline__ unsigned long long ullmax2(unsigned long long a, unsigned long long b){return a>b?a:b;}

// packed f32x2 ops (Blackwell). Per-lane rounding identical to scalar rn.
__device__ __forceinline__ unsigned long long pk2(float a, float b) {
    unsigned long long r; asm("mov.b64 %0, {%1, %2};" : "=l"(r) : "f"(a), "f"(b)); return r;
}
__device__ __forceinline__ void upk2(unsigned long long v, float& a, float& b) {
    asm("mov.b64 {%0, %1}, %2;" : "=f"(a), "=f"(b) : "l"(v));
}
__device__ __forceinline__ unsigned long long add2(unsigned long long a, unsigned long long b) {
    unsigned long long r; asm("add.rn.f32x2 %0, %1, %2;" : "=l"(r) : "l"(a), "l"(b)); return r;
}
__device__ __forceinline__ unsigned long long mul2(unsigned long long a, unsigned long long b) {
    unsigned long long r; asm("mul.rn.f32x2 %0, %1, %2;" : "=l"(r) : "l"(a), "l"(b)); return r;
}
__device__ __forceinline__ unsigned long long fma2(unsigned long long a, unsigned long long b, unsigned long long c) {
    unsigned long long r; asm("fma.rn.f32x2 %0, %1, %2, %3;" : "=l"(r) : "l"(a), "l"(b), "l"(c)); return r;
}

// warp-uniform reductions (sm_80+)
__device__ __forceinline__ unsigned redux_max(unsigned v) {
    unsigned r; asm volatile("redux.sync.max.u32 %0, %1, 0xffffffff;" : "=r"(r) : "r"(v)); return r;
}
__device__ __forceinline__ unsigned redux_min(unsigned v) {
    unsigned r; asm volatile("redux.sync.min.u32 %0, %1, 0xffffffff;" : "=r"(r) : "r"(v)); return r;
}

// shared-address + cluster comm helpers
__device__ __forceinline__ unsigned smem_u32addr(const void* p) {
    unsigned r;
    asm("{ .reg .u64 t; cvta.to.shared.u64 t, %1; cvt.u32.u64 %0, t; }" : "=r"(r) : "l"(p));
    return r;
}
__device__ __forceinline__ void st_cluster_u64(unsigned laddr, unsigned rank, unsigned long long v) {
    unsigned pa;
    asm volatile("mapa.shared::cluster.u32 %0, %1, %2;" : "=r"(pa) : "r"(laddr), "r"(rank));
    asm volatile("st.shared::cluster.u64 [%0], %1;" :: "r"(pa), "l"(v) : "memory");
}
__device__ __forceinline__ unsigned long long ld_volatile_smem_u64(unsigned laddr) {
    unsigned long long v;
    asm volatile("ld.volatile.shared.u64 %0, [%1];" : "=l"(v) : "r"(laddr) : "memory");
    return v;
}
#define CLUSTER_SYNC() do { \
    asm volatile("barrier.cluster.arrive.aligned;" ::: "memory"); \
    asm volatile("barrier.cluster.wait.aligned;" ::: "memory"); } while (0)

// ---------------- zero stats ----------------
__global__ void k_zero() {
    int t = blockIdx.x * blockDim.x + threadIdx.x;
    if (t < 6 * BB * 64) { g_sum[t] = 0.f; g_sq[t] = 0.f; }
}

// ---------------- transpose [B,3,N] -> [B,N,3] + copy pc to out ----------------
__global__ void k_transpose(const float* __restrict__ pc, const float* __restrict__ feat,
                            float* __restrict__ out_pc) {
    int i = blockIdx.x * blockDim.x + threadIdx.x;
    if (i < BB * 3 * N0) {
        int b = i / (3 * N0);
        int c = (i / N0) % 3;
        int n = i % N0;
        float v = pc[i];
        g_xyz0 [(b * N0 + n) * 3 + c] = v;
        g_feat0[(b * N0 + n) * 3 + c] = feat[i];
        out_pc[i] = v;
    }
}

// ---------------- stage-2 "FPS": provably the identity permutation --------------------
// FPS over xyz1 starting at index 0 selects positions 0..S2V-1 in order:
// selected positions have dist == 0 exactly, position i attains the global max,
// so first-max argmax returns i. xyz2 = xyz1[:,0:1024,:], fidx2 = iota.
__global__ void k_l2out(const float* __restrict__ xyz1,
                        float* __restrict__ xyz2,      // [b][1024][3]
                        float* __restrict__ out_pc2,   // [b][3][1024]
                        float* __restrict__ out_fidx2) // [b][1024]
{
    int t = blockIdx.x * blockDim.x + threadIdx.x;     // over BB*S2V
    int b = t / S2V;
    int i = t % S2V;
    float x = xyz1[((size_t)(b * S1V + i)) * 3 + 0];
    float y = xyz1[((size_t)(b * S1V + i)) * 3 + 1];
    float z = xyz1[((size_t)(b * S1V + i)) * 3 + 2];
    xyz2[((size_t)(b * S2V + i)) * 3 + 0] = x;
    xyz2[((size_t)(b * S2V + i)) * 3 + 1] = y;
    xyz2[((size_t)(b * S2V + i)) * 3 + 2] = z;
    out_pc2[b * 3 * S2V + 0 * S2V + i] = x;
    out_pc2[b * 3 * S2V + 1 * S2V + i] = y;
    out_pc2[b * 3 * S2V + 2 * S2V + i] = z;
    out_fidx2[b * S2V + i] = (float)i;
}

// ---------------- farthest point sampling (self-flagging packed tuple push) ----------
// LOAD-BEARING for bit-compat with the XLA reference (do not alter):
//   * distance form rn(fma(dz,dz, fma(dy,dy, rn(dx*dx)))) with dx = rn(x + (-cx))
//   * exact GLOBAL max, then 1-ulp tie window with minimum-GLOBAL-index selection
template <int N, int S, int T, int C, int SEG>
__global__ void __launch_bounds__(T, 1)
k_fps(const float* __restrict__ xyz,
      float* __restrict__ sel_xyz,   // [b][s][3]
      float* __restrict__ out_pc,    // [b][3][S]
      float* __restrict__ out_fidx,  // [b][S] as float
      int i0, int i1)
{
    extern __shared__ float sm[];
    float* sx = sm;
    float* sy = sm + N;
    float* sz = sm + 2 * N;
    float4* sel = (float4*)(sm + 3 * N);       // SEG staged rows (x,y,z,idx)
    constexpr int NW = T / 32;
    constexpr int CS = (C > 1) ? C : 1;
    __shared__ unsigned swmax[NW];
    __shared__ int s_argA[2], s_argB[2];
    __shared__ __align__(8) unsigned long long s_slot[2][CS];

    const int tid = threadIdx.x;
    const int lane = tid & 31;
    const int b = blockIdx.x / C;
    const int rank = blockIdx.x % C;
    constexpr int NL = N / C;        // points per CTA
    constexpr int PL = NL / T;       // points per thread
    constexpr int PAIRS = PL / 2;
    const int base = rank * NL;

    const float* xb = xyz + (size_t)b * N * 3;

    // full xyz copy (centroid lookup only)
    for (int p = tid; p < N; p += T) {
        sx[p] = xb[p * 3 + 0];
        sy[p] = xb[p * 3 + 1];
        sz[p] = xb[p * 3 + 2];
    }
    // register-resident slice
    unsigned long long X[PAIRS], Y[PAIRS], Z[PAIRS];
    float dist[PL];
#pragma unroll
    for (int jj = 0; jj < PAIRS; jj++) {
        int p0 = base + tid + jj * (2 * T);
        int p1 = p0 + T;
        X[jj] = pk2(xb[p0 * 3 + 0], xb[p1 * 3 + 0]);
        Y[jj] = pk2(xb[p0 * 3 + 1], xb[p1 * 3 + 1]);
        Z[jj] = pk2(xb[p0 * 3 + 2], xb[p1 * 3 + 2]);
        if (i0 == 0) { dist[2 * jj] = 1e10f; dist[2 * jj + 1] = 1e10f; }
        else { dist[2 * jj] = g_dist[b * N + p0]; dist[2 * jj + 1] = g_dist[b * N + p1]; }
    }
    int far = (i0 == 0) ? 0 : g_far[b];
    if (tid < 2) { s_argA[tid] = 0x7fffffff; s_argB[tid] = 0x7fffffff; }
    if (tid < 2 * CS) s_slot[tid >> (CS > 1 ? 3 : 0)][tid & (CS - 1)] = ~0ull;  // tag=1
    __syncthreads();
    if constexpr (C > 1) CLUSTER_SYNC();   // all CTAs' slots initialized

    const unsigned a_slot = smem_u32addr(&s_slot[0][0]);

    int ph = 0;
    for (int i = i0; i < i1; i++) {
        const int par = ph;
        float cx = sx[far], cy = sy[far], cz = sz[far];   // broadcast LDS
        if (tid == 0) sel[i - i0] = make_float4(cx, cy, cz, (float)far);
        const unsigned long long ncx2 = pk2(-cx, -cx);
        const unsigned long long ncy2 = pk2(-cy, -cy);
        const unsigned long long ncz2 = pk2(-cz, -cz);
        float mval = 0.f;
#pragma unroll
        for (int jj = 0; jj < PAIRS; jj++) {
            unsigned long long dx = add2(X[jj], ncx2);
            unsigned long long dy = add2(Y[jj], ncy2);
            unsigned long long dz = add2(Z[jj], ncz2);
            unsigned long long t  = mul2(dx, dx);
            t = fma2(dy, dy, t);
            t = fma2(dz, dz, t);
            float da, db; upk2(t, da, db);
            float n0 = fminf(dist[2 * jj],     da);
            float n1 = fminf(dist[2 * jj + 1], db);
            dist[2 * jj]     = n0;
            dist[2 * jj + 1] = n1;
            mval = fmaxf(mval, fmaxf(n0, n1));
        }
        // warp max then block max (dist>=0 -> float bits monotone, max exact)
        unsigned wm = redux_max(__float_as_uint(mval));
        if (lane == 0) swmax[tid >> 5] = wm;
        __syncthreads();                                    // B1
        const unsigned lmax = redux_max(swmax[lane & (NW - 1)]);
        if (lmax - __float_as_uint(mval) <= 1u) {           // candidate threads rescan
#pragma unroll
            for (int j = 0; j < PL; j++) {
                unsigned db = __float_as_uint(dist[j]);
                unsigned diff = lmax - db;
                if (diff <= 1u) {
                    int p = tid + (j >> 1) * (2 * T) + (j & 1) * T;
                    if (diff == 0) atomicMin(&s_argA[par], p);
                    else           atomicMin(&s_argB[par], p);
                }
            }
        }
        __syncthreads();                                    // B2: argA/argB final
        if constexpr (C > 1) {
            const unsigned long long tag = (unsigned long long)((i >> 1) & 1);
            if (tid < C) {   // lane r pushes this CTA's packed tuple to CTA r
                unsigned aA = (unsigned)s_argA[par];               // always valid (<2048)
                unsigned aB = (unsigned)s_argB[par];
                if (aB > 0xFFFEu) aB = 0xFFFFu;                    // sentinel
                unsigned long long pkt = (tag << 63)
                    | ((unsigned long long)lmax << 32)
                    | ((unsigned long long)aA << 16)
                    | (unsigned long long)aB;
                st_cluster_u64(a_slot + 8u * (par * C + rank), (unsigned)tid, pkt);
            }
            if (tid == 32) { s_argA[par ^ 1] = 0x7fffffff; s_argB[par ^ 1] = 0x7fffffff; }
            // poll the LOCAL slot copy; tag match == data valid (8B single-copy atomic)
            const unsigned myaddr = a_slot + 8u * (par * C + (lane & (C - 1)));
            unsigned long long v;
            do { v = ld_volatile_smem_u64(myaddr); } while ((v >> 63) != tag);
            unsigned mb = (unsigned)(v >> 32) & 0x7fffffffu;
            unsigned g = redux_max(mb);                      // exact global max
            unsigned cand = 0x7fffffffu;
            if (lane < C) {
                unsigned aA = (unsigned)(v >> 16) & 0xFFFFu;
                unsigned aB = (unsigned)v & 0xFFFFu;
                unsigned c2 = 0xFFFFu;
                if (mb == g)           c2 = aA < aB ? aA : aB;    // both bins in window
                else if (g - mb == 1u) c2 = aA;                   // only exact bin
                if (c2 != 0xFFFFu) cand = c2 + (unsigned)(lane * NL);
            }
            far = (int)redux_min(cand);                      // min global index
        } else {
            int aA = s_argA[par], aB = s_argB[par];
            far = aA < aB ? aA : aB;                         // min index within window
            if (tid == 32) { s_argA[par ^ 1] = 0x7fffffff; s_argB[par ^ 1] = 0x7fffffff; }
        }
        ph ^= 1;
    }

    if (i1 < S) {   // persist segment state
#pragma unroll
        for (int j = 0; j < PL; j++)
            g_dist[b * N + base + tid + (j >> 1) * (2 * T) + (j & 1) * T] = dist[j];
        if (rank == 0 && tid == 0) g_far[b] = far;
    }
    if (rank == 0) {    // bulk, coalesced output write for positions [i0, i1)
        for (int r = tid; r < i1 - i0; r += T) {
            float4 w = sel[r];
            int i = i0 + r;
            sel_xyz[((size_t)(b * S + i)) * 3 + 0] = w.x;
            sel_xyz[((size_t)(b * S + i)) * 3 + 1] = w.y;
            sel_xyz[((size_t)(b * S + i)) * 3 + 2] = w.z;
            out_pc[b * 3 * S + 0 * S + i] = w.x;
            out_pc[b * 3 * S + 1 * S + i] = w.y;
            out_pc[b * 3 * S + 2 * S + i] = w.z;
            out_fidx[b * S + i] = w.w;
        }
    }
    if constexpr (C > 1) CLUSTER_SYNC();   // exit safety: peers' smem stays live
}

// ---------------- kNN (k=32): warp top-32, hybrid single-insert / bitonic ----------
__device__ __forceinline__ unsigned long long bitonic_sort32(unsigned long long v, int lane) {
#pragma unroll
    for (int k = 2; k <= 32; k <<= 1) {
#pragma unroll
        for (int j = k >> 1; j; j >>= 1) {
            unsigned long long o = __shfl_xor_sync(0xffffffffu, v, j);
            bool up    = (lane & k) == 0;
            bool lower = (lane & j) == 0;
            v = (lower == up) ? ullmin2(v, o) : ullmax2(v, o);
        }
    }
    return v;
}
__device__ __forceinline__ unsigned long long bitonic_merge32(unsigned long long v, int lane) {
#pragma unroll
    for (int j = 16; j; j >>= 1) {
        unsigned long long o = __shfl_xor_sync(0xffffffffu, v, j);
        v = ((lane & j) == 0) ? ullmin2(v, o) : ullmax2(v, o);
    }
    return v;
}

template <int N, int S, int CHUNK>
__global__ void k_knn(const float* __restrict__ q, const float* __restrict__ ref,
                      int* __restrict__ nidx, int q0, int nq)
{
    __shared__ float sref[CHUNK * 3];
    const int tid  = threadIdx.x;
    const int lane = tid & 31;
    const int warp = tid >> 5;
    const int per_b = nq / 8;
    const int b = blockIdx.x / per_b;
    const int s = q0 + (blockIdx.x % per_b) * 8 + warp;

    const float qx = q[(b * S + s) * 3 + 0];
    const float qy = q[(b * S + s) * 3 + 1];
    const float qz = q[(b * S + s) * 3 + 2];
    const float qq = fmaf(qz, qz, fmaf(qy, qy, __fmul_rn(qx, qx)));

    unsigned long long topv = ~0ull;   // distributed sorted top-32 (lane k = k-th best)
    unsigned long long thr  = ~0ull;   // lane-31 value

    const float* rb = ref + (size_t)b * N * 3;
    for (int ch = 0; ch < N; ch += CHUNK) {
        for (int i = tid; i < CHUNK * 3; i += 256) sref[i] = rb[ch * 3 + i];
        __syncthreads();
#pragma unroll 2
        for (int c = 0; c < CHUNK / 32; c++) {
            int il = c * 32 + lane;
            float rx = sref[il * 3 + 0];
            float ry = sref[il * 3 + 1];
            float rz = sref[il * 3 + 2];
            float dot = fmaf(qz, rz, fmaf(qy, ry, __fmul_rn(qx, rx)));
            float rr  = fmaf(rz, rz, fmaf(ry, ry, __fmul_rn(rx, rx)));
            float d = __fadd_rn(__fsub_rn(qq, __fmul_rn(2.f, dot)), rr);
            unsigned long long key = ((unsigned long long)fkey(d) << 32) | (unsigned)(ch + il);
            unsigned hitm = __ballot_sync(0xffffffffu, key < thr);
            if (hitm) {
                int h = __popc(hitm);
                if (h <= 4) {
                    // serialized exact insertion: broadcast key, rank via ballot,
                    // shift-insert with one shfl_up (keys unique -> no tie issues)
                    while (hitm) {
                        int src = __ffs(hitm) - 1;
                        hitm &= hitm - 1;
                        unsigned long long kk = __shfl_sync(0xffffffffu, key, src);
                        unsigned gtm = __ballot_sync(0xffffffffu, topv > kk);
                        if (gtm) {   // should always be true (kk < topv[31])
                            int pos = __ffs(gtm) - 1;
                            unsigned long long up = __shfl_up_sync(0xffffffffu, topv, 1);
                            topv = (lane < pos) ? topv : (lane == pos ? kk : up);
                        }
                    }
                } else {
                    unsigned long long v = bitonic_sort32(key, lane);      // batch ascending
                    unsigned long long w = __shfl_xor_sync(0xffffffffu, v, 31); // reversed
                    topv = bitonic_merge32(ullmin2(topv, w), lane);
                }
                thr = __shfl_sync(0xffffffffu, topv, 31);
            }
        }
        __syncthreads();
    }
    // lane k holds the k-th nearest (ascending d, ties by lower index)
    nidx[((size_t)(b * S + s)) * KK + lane] = (int)(unsigned)(topv & 0xffffffffu);
}

// ---------------- gather + first 1x1 conv + stats (chunkable over s) ----------------
template <int FDIM, int COUT, int SS, int NREF>
__global__ void k_gather_mm(const float* __restrict__ refxyz,
                            const float* __restrict__ reffeat,
                            const float* __restrict__ newxyz,
                            const int* __restrict__ nidx,
                            const float* __restrict__ W,
                            float* __restrict__ y,
                            float* __restrict__ sum, float* __restrict__ sq,
                            int q0, int nq)
{
    constexpr int CIN = 3 + FDIM;
    __shared__ float sW[CIN * COUT];
    for (int i = threadIdx.x; i < CIN * COUT; i += blockDim.x) sW[i] = W[i];
    __syncthreads();

    int r0 = blockIdx.x * blockDim.x + threadIdx.x;
    int per_b = nq * KK;
    int b = r0 / per_b;
    int rem = q0 * KK + (r0 - b * per_b);
    int s = rem / KK;
    int n = nidx[(size_t)b * (SS * KK) + rem];

    float in[CIN];
#pragma unroll
    for (int c = 0; c < 3; c++)
        in[c] = refxyz[((size_t)(b * NREF + n)) * 3 + c] - newxyz[((size_t)(b * SS + s)) * 3 + c];
#pragma unroll
    for (int j = 0; j < FDIM; j++)
        in[3 + j] = reffeat[((size_t)(b * NREF + n)) * FDIM + j];

    float acc[COUT];
#pragma unroll
    for (int c = 0; c < COUT; c++) acc[c] = 0.f;
#pragma unroll
    for (int j = 0; j < CIN; j++) {
        float v = in[j];
#pragma unroll
        for (int c = 0; c < COUT; c++) acc[c] = fmaf(v, sW[j * COUT + c], acc[c]);
    }
#pragma unroll
    for (int c = 0; c < COUT; c++)
        y[((size_t)(b * COUT + c)) * (SS * KK) + rem] = acc[c];

    int lane = threadIdx.x & 31;
#pragma unroll
    for (int c = 0; c < COUT; c++) {
        float v = acc[c], v2 = v * v;
#pragma unroll
        for (int o = 16; o; o >>= 1) {
            v  += __shfl_down_sync(0xffffffffu, v,  o);
            v2 += __shfl_down_sync(0xffffffffu, v2, o);
        }
        if (lane == 0) { atomicAdd(&sum[b * 64 + c], v); atomicAdd(&sq[b * 64 + c], v2); }
    }
}

// ---------------- instance-norm + relu + 1x1 conv + stats ----------------
template <int CIN, int COUT, int SS>
__global__ void k_mm(const float* __restrict__ x, const float* __restrict__ W,
                     const float* __restrict__ sumIn, const float* __restrict__ sqIn,
                     float* __restrict__ y,
                     float* __restrict__ sumOut, float* __restrict__ sqOut)
{
    __shared__ float sW[CIN * COUT];
    __shared__ float sMu[CIN], sInv[CIN];
    int r = blockIdx.x * blockDim.x + threadIdx.x;
    int b = r / (SS * KK);
    int rem = r - b * (SS * KK);
    for (int i = threadIdx.x; i < CIN * COUT; i += blockDim.x) sW[i] = W[i];
    if (threadIdx.x < CIN) {
        float cnt = (float)(SS * KK);
        float mu = sumIn[b * 64 + threadIdx.x] / cnt;
        float var = sqIn[b * 64 + threadIdx.x] / cnt - mu * mu;
        sMu[threadIdx.x] = mu;
        sInv[threadIdx.x] = rsqrtf(var + 1e-5f);
    }
    __syncthreads();

    float acc[COUT];
#pragma unroll
    for (int c = 0; c < COUT; c++) acc[c] = 0.f;
#pragma unroll
    for (int j = 0; j < CIN; j++) {
        float v = x[((size_t)(b * CIN + j)) * (SS * KK) + rem];
        v = fmaxf(0.f, (v - sMu[j]) * sInv[j]);
#pragma unroll
        for (int c = 0; c < COUT; c++) acc[c] = fmaf(v, sW[j * COUT + c], acc[c]);
    }
#pragma unroll
    for (int c = 0; c < COUT; c++)
        y[((size_t)(b * COUT + c)) * (SS * KK) + rem] = acc[c];

    int lane = threadIdx.x & 31;
#pragma unroll
    for (int c = 0; c < COUT; c++) {
        float v = acc[c], v2 = v * v;
#pragma unroll
        for (int o = 16; o; o >>= 1) {
            v  += __shfl_down_sync(0xffffffffu, v,  o);
            v2 += __shfl_down_sync(0xffffffffu, v2, o);
        }
        if (lane == 0) { atomicAdd(&sumOut[b * 64 + c], v); atomicAdd(&sqOut[b * 64 + c], v2); }
    }
}

// ---------------- instance-norm + relu + maxpool over K ----------------
template <int C, int SS, bool CHMAJOR>
__global__ void k_maxpool(const float* __restrict__ x,
                          const float* __restrict__ sumIn, const float* __restrict__ sqIn,
                          float* __restrict__ outp)
{
    int t = blockIdx.x * blockDim.x + threadIdx.x;
    int s = t % SS;
    int c = (t / SS) % C;
    int b = t / (SS * C);
    float cnt = (float)(SS * KK);
    float mu = sumIn[b * 64 + c] / cnt;
    float var = sqIn[b * 64 + c] / cnt - mu * mu;
    float inv = rsqrtf(var + 1e-5f);

    const float4* p = reinterpret_cast<const float4*>(
        x + ((size_t)(b * C + c)) * (SS * KK) + (size_t)s * KK);
    float m = -3.4e38f;
#pragma unroll
    for (int qv = 0; qv < KK / 4; qv++) {
        float4 v = p[qv];
        m = fmaxf(m, fmaxf(fmaxf(v.x, v.y), fmaxf(v.z, v.w)));
    }
    float outv = fmaxf(0.f, (m - mu) * inv);
    if (CHMAJOR) outp[(b * C + c) * SS + s] = outv;
    else         outp[(b * SS + s) * C + c] = outv;
}

// ---------------- launch ----------------
extern "C" void kernel_launch(void* const* d_in, const int* in_sizes, int n_in,
                              void* d_out, int out_size)
{
    const float* pc     = (const float*)d_in[0];
    const float* feat   = (const float*)d_in[1];
    const float* sa1_w1 = (const float*)d_in[2];
    const float* sa1_w2 = (const float*)d_in[3];
    const float* sa1_w3 = (const float*)d_in[4];
    const float* sa2_w1 = (const float*)d_in[5];
    const float* sa2_w2 = (const float*)d_in[6];
    const float* sa2_w3 = (const float*)d_in[7];

    float* out = (float*)d_out;
    float* out_pc      = out;
    float* out_pc_l1   = out + 196608;
    float* out_pc_l2   = out + 196608 + 24576;
    float* out_feat_l2 = out + 196608 + 24576 + 12288;
    float* out_fidx1   = out + 196608 + 24576 + 12288 + 262144;
    float* out_fidx2   = out + 196608 + 24576 + 12288 + 262144 + 8192;

    float *xyz0, *feat0, *xyz1, *xyz2, *feat1, *bufA, *bufB, *sum, *sq;
    int *nidx1, *nidx2;
    cudaGetSymbolAddress((void**)&xyz0,  g_xyz0);
    cudaGetSymbolAddress((void**)&feat0, g_feat0);
    cudaGetSymbolAddress((void**)&xyz1,  g_xyz1);
    cudaGetSymbolAddress((void**)&xyz2,  g_xyz2);
    cudaGetSymbolAddress((void**)&feat1, g_feat1);
    cudaGetSymbolAddress((void**)&bufA,  g_bufA);
    cudaGetSymbolAddress((void**)&bufB,  g_bufB);
    cudaGetSymbolAddress((void**)&sum,   g_sum);
    cudaGetSymbolAddress((void**)&sq,    g_sq);
    cudaGetSymbolAddress((void**)&nidx1, g_nidx1);
    cudaGetSymbolAddress((void**)&nidx2, g_nidx2);

    constexpr int CL = 8;                            // cluster size for stage-1 FPS
    constexpr int SMEM1 = 3 * N0 * 4 + 512 * 16;     // full xyz copy + staged rows = 200KB
    cudaFuncSetAttribute((const void*)k_fps<N0, S1V, 512, CL, 512>,
                         cudaFuncAttributeMaxDynamicSharedMemorySize, SMEM1);

    // one-time side stream + events (host objects only; no device allocation)
    static cudaStream_t s1 = nullptr;
    static cudaEvent_t evSeg[4], evPool1;
    if (!s1) {
        cudaStreamCreateWithFlags(&s1, cudaStreamNonBlocking);
        for (int i = 0; i < 4; i++) cudaEventCreateWithFlags(&evSeg[i], cudaEventDisableTiming);
        cudaEventCreateWithFlags(&evPool1, cudaEventDisableTiming);
    }

    k_zero<<<6, 256>>>();
    k_transpose<<<768, 256>>>(pc, feat, out_pc);

    // ---- FPS1: 4 cluster-parallel segments on main stream; kNN1/gather1 trail on s1 ----
    for (int seg = 0; seg < 4; seg++) {
        cudaLaunchConfig_t cfg = {};
        cfg.gridDim = dim3(BB * CL, 1, 1);
        cfg.blockDim = dim3(512, 1, 1);
        cfg.dynamicSmemBytes = SMEM1;
        cfg.stream = 0;
        cudaLaunchAttribute attrs[1];
        attrs[0].id = cudaLaunchAttributeClusterDimension;
        attrs[0].val.clusterDim.x = CL;
        attrs[0].val.clusterDim.y = 1;
        attrs[0].val.clusterDim.z = 1;
        cfg.attrs = attrs;
        cfg.numAttrs = 1;
        cudaLaunchKernelEx(&cfg, k_fps<N0, S1V, 512, CL, 512>,
                           (const float*)xyz0, xyz1, out_pc_l1, out_fidx1,
                           seg * 512, (seg + 1) * 512);
        cudaEventRecord(evSeg[seg], 0);
    }
    for (int seg = 0; seg < 4; seg++) {
        cudaStreamWaitEvent(s1, evSeg[seg], 0);
        k_knn<N0, S1V, 2048><<<BB * 512 / 8, 256, 0, s1>>>(xyz1, xyz0, nidx1, seg * 512, 512);
        k_gather_mm<3, 32, S1V, N0><<<(BB * 512 * KK) / 256, 256, 0, s1>>>(
            xyz0, feat0, xyz1, nidx1, sa1_w1, bufA,
            sum + 0 * BB * 64, sq + 0 * BB * 64, seg * 512, 512);
    }
    // stage-1 MLP tail on s1
    k_mm<32, 32, S1V><<<(BB * S1V * KK) / 256, 256, 0, s1>>>(
        bufA, sa1_w2, sum + 0 * BB * 64, sq + 0 * BB * 64, bufB,
        sum + 1 * BB * 64, sq + 1 * BB * 64);
    k_mm<32, 32, S1V><<<(BB * S1V * KK) / 256, 256, 0, s1>>>(
        bufB, sa1_w3, sum + 1 * BB * 64, sq + 1 * BB * 64, bufA,
        sum + 2 * BB * 64, sq + 2 * BB * 64);
    k_maxpool<32, S1V, false><<<(BB * 32 * S1V) / 256, 256, 0, s1>>>(
        bufA, sum + 2 * BB * 64, sq + 2 * BB * 64, feat1);
    cudaEventRecord(evPool1, s1);

    // ---- stage-2 sampling is the identity: copy prefix + iota, then kNN2 ----
    k_l2out<<<(BB * S2V) / 256, 256>>>(xyz1, xyz2, out_pc_l2, out_fidx2);
    k_knn<S1V, S2V, 2048><<<BB * S2V / 8, 256>>>(xyz2, xyz1, nidx2, 0, S2V);

    // ---- join, then stage-2 MLP on main stream ----
    cudaStreamWaitEvent(0, evPool1, 0);
    k_gather_mm<32, 64, S2V, S1V><<<(BB * S2V * KK) / 256, 256>>>(
        xyz1, feat1, xyz2, nidx2, sa2_w1, bufA,
        sum + 3 * BB * 64, sq + 3 * BB * 64, 0, S2V);
    k_mm<64, 64, S2V><<<(BB * S2V * KK) / 256, 256>>>(
        bufA, sa2_w2, sum + 3 * BB * 64, sq + 3 * BB * 64, bufB,
        sum + 4 * BB * 64, sq + 4 * BB * 64);
    k_mm<64, 64, S2V><<<(BB * S2V * KK) / 256, 256>>>(
        bufB, sa2_w3, sum + 4 * BB * 64, sq + 4 * BB * 64, bufA,
        sum + 5 * BB * 64, sq + 5 * BB * 64);
    k_maxpool<64, S2V, true><<<(BB * 64 * S2V) / 256, 256>>>(
        bufA, sum + 5 * BB * 64, sq + 5 * BB * 64, out_feat_l2);
}